// round 14
// baseline (speedup 1.0000x reference)
#include <cuda_runtime.h>
#include <math.h>

// ---------------- problem constants ----------------
#define LSEQ   1024
#define NBATCH 2
#define TT     (NBATCH*LSEQ)   // 2048 tokens
#define DM     512
#define DI     1024
#define DFF    2048
#define DS     16
#define DTR    32
#define NC     32              // scan chunks
#define LC     (LSEQ/NC)       // 32 steps per chunk

// ---------------- scratch ----------------
__device__ float g_xz[2][(size_t)TT*2*DI];
__device__ float g_xm[2][(size_t)TT*DI];
__device__ float g_dbc[2][(size_t)TT*64];
__device__ float g_y[2][(size_t)TT*DI];
__device__ float g_dirout[2][(size_t)TT*DM];
__device__ float g_res[(size_t)TT*DM];
__device__ float g_hbuf[(size_t)TT*DFF];
__device__ float g_ff[2][(size_t)TT*DM];      // two split-K partial buffers
__device__ float g_P [(size_t)2*NBATCH*NC*DS*DI];
__device__ float g_q [(size_t)2*NBATCH*NC*DS*DI];
__device__ float g_h0[(size_t)2*NBATCH*NC*DS*DI];

// ---------------- TF32 tensor-core GEMM ----------------
// C[M,N] = A[M,K] * W[N,K]^T ; A row-major (lda), W row-major (ldb).
// CTA tile 128x128xKT32, 512 threads, 16 warps of 32x32 warp tiles.
// SMEM in MMA-fragment-interleaved layout, XOR bank swizzle; frag loads are
// 1x LDS.128 (A) / 1x LDS.64 (B), conflict-free.
struct GemmArgs { const float* A; const float* W; const float* bias; float* C; int flipA; int flipC; };

#define KT 32

__device__ __forceinline__ unsigned f2tf32(float f) {
    unsigned u; asm("cvt.rna.tf32.f32 %0, %1;" : "=r"(u) : "f"(f)); return u;
}
__device__ __forceinline__ float cvtf(float f) { return __uint_as_float(f2tf32(f)); }

__global__ __launch_bounds__(512,1) void gemm_tf32(
    GemmArgs ga0, GemmArgs ga1, int M, int N, int K, int lda, int ldb, int ldc, int mode, int S)
{
    extern __shared__ float sh[];
    float* shA = sh; float* shB = sh + 8192;
    const int z = blockIdx.z;
    const int dir = z / S, sk = z - dir*S;
    const GemmArgs g = dir ? ga1 : ga0;
    const int kLen = K/S, kOff = sk*kLen;
    const int tid = threadIdx.x, lane = tid&31, w = tid>>5;
    const int gq = lane>>2, tq = lane&3;
    const int wm = (w&3)*32, wn = (w>>2)*32;
    const int wgm = (w&3)*2, wgn = (w>>2)*4;
    const int m0 = blockIdx.y*128, n0 = blockIdx.x*128;
    const int lr = tid>>3, lc4 = (tid&7)*4;
    const int ksl = lc4>>3, khalf = (lc4>>2)&1;

    size_t aRow[2], bRow[2];
    #pragma unroll
    for (int i=0;i<2;i++){
        int m = m0+lr+i*64;
        int r = m;
        if (g.flipA) r = (m&~(LSEQ-1)) + (LSEQ-1 - (m&(LSEQ-1)));
        aRow[i] = (size_t)r*lda + kOff;
    }
    #pragma unroll
    for (int i=0;i<2;i++){ int n=n0+lr+i*64; if(n>=N)n=N-1; bRow[i]=(size_t)n*ldb+kOff; }
    int aBase[2], bBase[2];
    #pragma unroll
    for (int i=0;i<2;i++){
        int m=lr+i*64; int gg=m>>4, gq_=m&7, mh=(m>>3)&1;
        aBase[i]=((((gg*4+ksl)*8+gq_)<<4))+khalf*2+mh;
        int gb=m>>3, gqb=m&7;
        bBase[i]=((((gb*4+ksl)*8+gqb)<<3))+khalf;
    }
    float4 aReg[2], bReg[2];
    #pragma unroll
    for (int i=0;i<2;i++) aReg[i]=*(const float4*)(g.A+aRow[i]+lc4);
    #pragma unroll
    for (int i=0;i<2;i++) bReg[i]=*(const float4*)(g.W+bRow[i]+lc4);
    float c[2][4][4];
    #pragma unroll
    for (int mt=0;mt<2;mt++) for (int nt=0;nt<4;nt++) for (int r=0;r<4;r++) c[mt][nt][r]=0.f;
    int buf=0;
    #pragma unroll
    for (int i=0;i<2;i++){
        float* p=shA+aBase[i]; float v[4]={aReg[i].x,aReg[i].y,aReg[i].z,aReg[i].w};
        #pragma unroll
        for(int j=0;j<4;j++) p[(j^ksl)<<2]=cvtf(v[j]);
        float* q=shB+bBase[i]; float u[4]={bReg[i].x,bReg[i].y,bReg[i].z,bReg[i].w};
        #pragma unroll
        for(int j=0;j<4;j++) q[(j^ksl)<<1]=cvtf(u[j]);
    }
    __syncthreads();
    for (int kt=0; kt<kLen; kt+=KT){
        bool more = (kt+KT)<kLen;
        if (more){
            #pragma unroll
            for (int i=0;i<2;i++) aReg[i]=*(const float4*)(g.A+aRow[i]+kt+KT+lc4);
            #pragma unroll
            for (int i=0;i<2;i++) bReg[i]=*(const float4*)(g.W+bRow[i]+kt+KT+lc4);
        }
        const float4* Ap=(const float4*)(shA+buf*4096);
        const float2* Bp=(const float2*)(shB+buf*4096);
        #pragma unroll
        for (int ks=0;ks<4;ks++){
            const int tqp=tq^ks;
            float4 av[2]; float2 bv[4];
            #pragma unroll
            for (int mt=0;mt<2;mt++) av[mt]=Ap[(((wgm+mt)*4+ks)*8+gq)*4+tqp];
            #pragma unroll
            for (int nt=0;nt<4;nt++) bv[nt]=Bp[(((wgn+nt)*4+ks)*8+gq)*4+tqp];
            #pragma unroll
            for (int mt=0;mt<2;mt++)
                #pragma unroll
                for (int nt=0;nt<4;nt++)
                    asm volatile("mma.sync.aligned.m16n8k8.row.col.f32.tf32.tf32.f32 {%0,%1,%2,%3}, {%4,%5,%6,%7}, {%8,%9}, {%0,%1,%2,%3};"
                        : "+f"(c[mt][nt][0]),"+f"(c[mt][nt][1]),"+f"(c[mt][nt][2]),"+f"(c[mt][nt][3])
                        : "r"(__float_as_uint(av[mt].x)),"r"(__float_as_uint(av[mt].y)),
                          "r"(__float_as_uint(av[mt].z)),"r"(__float_as_uint(av[mt].w)),
                          "r"(__float_as_uint(bv[nt].x)),"r"(__float_as_uint(bv[nt].y)));
        }
        if (more){
            int nb=buf^1;
            #pragma unroll
            for (int i=0;i<2;i++){
                float* p=shA+nb*4096+aBase[i]; float v[4]={aReg[i].x,aReg[i].y,aReg[i].z,aReg[i].w};
                #pragma unroll
                for(int j=0;j<4;j++) p[(j^ksl)<<2]=cvtf(v[j]);
                float* q=shB+nb*4096+bBase[i]; float u[4]={bReg[i].x,bReg[i].y,bReg[i].z,bReg[i].w};
                #pragma unroll
                for(int j=0;j<4;j++) q[(j^ksl)<<1]=cvtf(u[j]);
            }
        }
        __syncthreads();
        buf^=1;
    }
    #pragma unroll
    for (int mt=0;mt<2;mt++)
        #pragma unroll
        for (int half=0;half<2;half++){
            int m = m0 + wm + mt*16 + gq + half*8;
            int orow = m;
            if (g.flipC) orow = (m&~(LSEQ-1)) + (LSEQ-1 - (m&(LSEQ-1)));
            #pragma unroll
            for (int nt=0;nt<4;nt++){
                int col = n0 + wn + nt*8 + 2*tq;
                if (col>=N) continue;
                float v0=c[mt][nt][half*2+0], v1=c[mt][nt][half*2+1];
                if (S>1){
                    atomicAdd(g.C+(size_t)orow*ldc+col, v0);
                    atomicAdd(g.C+(size_t)orow*ldc+col+1, v1);
                } else {
                    if (mode){ v0+=g.bias[col]; v1+=g.bias[col+1]; }
                    if (mode==1){ v0=fmaxf(v0,0.f); v1=fmaxf(v1,0.f); }
                    *(float2*)(g.C+(size_t)orow*ldc+col)=make_float2(v0,v1);
                }
            }
        }
}

// ---------------- causal depthwise conv (width 4) + silu, 4 t per thread ----------------
__global__ void conv_silu_k(const float* __restrict__ fW, const float* __restrict__ fb,
                            const float* __restrict__ bW, const float* __restrict__ bb)
{
    int dir = blockIdx.y;
    size_t idx = (size_t)blockIdx.x*blockDim.x + threadIdx.x;   // over TT*DI/4
    int e  = (int)(idx % DI);
    int tg = (int)(idx / DI);
    int t0 = tg*4;
    int l0 = t0 & (LSEQ-1);
    const float* cw = dir ? bW : fW;
    const float* cb = dir ? bb : fb;
    const float* xz = g_xz[dir];
    float w0=cw[e*4+0], w1=cw[e*4+1], w2=cw[e*4+2], w3=cw[e*4+3];
    float bias = cb[e];
    float v[7];
    #pragma unroll
    for (int k = 0; k < 7; k++) {
        int off = k - 3;                 // input t offset -3..+3
        v[k] = (l0 + off >= 0) ? xz[(size_t)(t0+off)*(2*DI) + e] : 0.f;
    }
    float* xm = g_xm[dir];
    #pragma unroll
    for (int j = 0; j < 4; j++) {
        float acc = bias + v[j]*w0 + v[j+1]*w1 + v[j+2]*w2 + v[j+3]*w3;
        xm[(size_t)(t0+j)*DI + e] = acc / (1.f + __expf(-acc));
    }
}

// ---------------- scan helpers ----------------
__device__ __forceinline__ void load_negA(const float* Alog, int e, float* negA, bool& fast){
    const float4* Ar = (const float4*)(Alog + (size_t)e*16);
    #pragma unroll
    for (int s4=0;s4<4;s4++){
        float4 v=Ar[s4];
        negA[s4*4+0]=-__expf(v.x); negA[s4*4+1]=-__expf(v.y);
        negA[s4*4+2]=-__expf(v.z); negA[s4*4+3]=-__expf(v.w);
    }
    fast = true;
    #pragma unroll
    for (int s=0;s<16;s++) fast = fast && (fabsf(negA[s]+(float)(s+1)) <= 1e-3f*(float)(s+1));
}
__device__ __forceinline__ void comp_dA(float d, const float* negA, bool fast, float* da){
    if (fast){ float r=__expf(-d); da[0]=r;
        #pragma unroll
        for (int s=1;s<16;s++) da[s]=da[s-1]*r;
    } else {
        #pragma unroll
        for (int s=0;s<16;s++) da[s]=__expf(d*negA[s]);
    }
}
// delta from raw dt row + per-channel dtW row (fused softplus)
__device__ __forceinline__ float comp_delta(const float4* R4, const float* wr, float dtb){
    float dot = dtb;
    #pragma unroll
    for (int j=0;j<8;j++){
        float4 v = R4[j];
        dot += v.x*wr[j*4+0] + v.y*wr[j*4+1] + v.z*wr[j*4+2] + v.w*wr[j*4+3];
    }
    return (dot > 20.f) ? dot : __logf(1.f + __expf(dot));
}

// ---------------- scan phase A (delta fused) ----------------
__global__ __launch_bounds__(256,2) void scanA_k(const float* __restrict__ fA, const float* __restrict__ bA,
                                                 const float* __restrict__ fdtW, const float* __restrict__ bdtW,
                                                 const float* __restrict__ fdtB, const float* __restrict__ bdtB)
{
    int e = blockIdx.x*256+threadIdx.x, c = blockIdx.y;
    int dir = blockIdx.z>>1, b = blockIdx.z&1;
    const float* Alog = dir?bA:fA;
    const float* dtW  = dir?bdtW:fdtW;
    const float  dtb  = (dir?bdtB:fdtB)[e];
    const float* xm = g_xm[dir]; const float* dbc = g_dbc[dir];
    float negA[16]; bool fast; load_negA(Alog,e,negA,fast);
    float wr[32];
    {
        const float4* W4 = (const float4*)(dtW + (size_t)e*DTR);
        #pragma unroll
        for (int j=0;j<8;j++){ float4 v=W4[j]; wr[j*4]=v.x;wr[j*4+1]=v.y;wr[j*4+2]=v.z;wr[j*4+3]=v.w; }
    }
    float P[16], q[16];
    #pragma unroll
    for (int s=0;s<16;s++){ P[s]=1.f; q[s]=0.f; }
    int l0=c*LC;
    for (int l=l0;l<l0+LC;l++){
        int t=(b<<10)+l; size_t te=(size_t)t*DI+e;
        const float4* R4=(const float4*)(dbc+(size_t)t*64);
        float d = comp_delta(R4, wr, dtb);
        float xv=xm[te], dx=d*xv;
        float Bsx[16];
        #pragma unroll
        for (int s4=0;s4<4;s4++){ float4 v=R4[8+s4]; Bsx[s4*4]=v.x;Bsx[s4*4+1]=v.y;Bsx[s4*4+2]=v.z;Bsx[s4*4+3]=v.w; }
        float da[16]; comp_dA(d,negA,fast,da);
        #pragma unroll
        for (int s=0;s<16;s++){ q[s]=da[s]*q[s]+dx*Bsx[s]; P[s]*=da[s]; }
    }
    size_t base=(((size_t)(dir*2+b)*NC+c)*16)*DI+e;
    #pragma unroll
    for (int s=0;s<16;s++){ g_P[base+(size_t)s*DI]=P[s]; g_q[base+(size_t)s*DI]=q[s]; }
}

// ---------------- scan phase B ----------------
__global__ void scanB_k(){
    int idx = blockIdx.x*256+threadIdx.x;
    int e=idx&(DI-1), s=(idx>>10)&15, cb=idx>>14;
    float h=0.f;
    #pragma unroll 4
    for (int c=0;c<NC;c++){
        size_t base=(((size_t)cb*NC+c)*16+s)*DI+e;
        g_h0[base]=h; h=g_P[base]*h+g_q[base];
    }
}

// ---------------- scan phase C (delta fused) ----------------
__global__ __launch_bounds__(256,2) void scanC_k(const float* __restrict__ fA, const float* __restrict__ bA,
                                                 const float* __restrict__ fD, const float* __restrict__ bD,
                                                 const float* __restrict__ fdtW, const float* __restrict__ bdtW,
                                                 const float* __restrict__ fdtB, const float* __restrict__ bdtB)
{
    int e = blockIdx.x*256+threadIdx.x, c = blockIdx.y;
    int dir = blockIdx.z>>1, b = blockIdx.z&1;
    const float* Alog = dir?bA:fA; const float* Dp = dir?bD:fD;
    const float* dtW  = dir?bdtW:fdtW;
    const float  dtb  = (dir?bdtB:fdtB)[e];
    const float* xm = g_xm[dir];
    const float* dbc = g_dbc[dir]; const float* xz = g_xz[dir];
    float* yout = g_y[dir];
    float negA[16]; bool fast; load_negA(Alog,e,negA,fast);
    float wr[32];
    {
        const float4* W4 = (const float4*)(dtW + (size_t)e*DTR);
        #pragma unroll
        for (int j=0;j<8;j++){ float4 v=W4[j]; wr[j*4]=v.x;wr[j*4+1]=v.y;wr[j*4+2]=v.z;wr[j*4+3]=v.w; }
    }
    float h[16];
    size_t hb=(((size_t)(dir*2+b)*NC+c)*16)*DI+e;
    #pragma unroll
    for (int s=0;s<16;s++) h[s]=g_h0[hb+(size_t)s*DI];
    float Dpe=Dp[e];
    int l0=c*LC;
    for (int l=l0;l<l0+LC;l++){
        int t=(b<<10)+l; size_t te=(size_t)t*DI+e;
        const float4* R4=(const float4*)(dbc+(size_t)t*64);
        float d = comp_delta(R4, wr, dtb);
        float xv=xm[te], dx=d*xv;
        float Bsx[16], Cs[16];
        #pragma unroll
        for (int s4=0;s4<4;s4++){
            float4 v=R4[8+s4];  Bsx[s4*4]=v.x;Bsx[s4*4+1]=v.y;Bsx[s4*4+2]=v.z;Bsx[s4*4+3]=v.w;
            float4 w=R4[12+s4]; Cs[s4*4]=w.x;Cs[s4*4+1]=w.y;Cs[s4*4+2]=w.z;Cs[s4*4+3]=w.w;
        }
        float da[16]; comp_dA(d,negA,fast,da);
        float y=0.f;
        #pragma unroll
        for (int s=0;s<16;s++){ h[s]=da[s]*h[s]+dx*Bsx[s]; y+=h[s]*Cs[s]; }
        float zv=xz[(size_t)t*(2*DI)+DI+e];
        float sil=zv/(1.f+__expf(-zv));
        yout[te]=(y+xv*Dpe)*sil;
    }
}

// ---------------- LN1 + LN2 + sum ----------------
__global__ void ln12_k(const float* __restrict__ x,
                       const float* __restrict__ g1, const float* __restrict__ b1,
                       const float* __restrict__ g2, const float* __restrict__ b2)
{
    __shared__ float red[4][4];
    int t=blockIdx.x, tid=threadIdx.x;
    float4 xv=((const float4*)(x+(size_t)t*DM))[tid];
    float4 fv=((const float4*)(g_dirout[0]+(size_t)t*DM))[tid];
    float4 wv=((const float4*)(g_dirout[1]+(size_t)t*DM))[tid];
    float a[4]={xv.x+fv.x,xv.y+fv.y,xv.z+fv.z,xv.w+fv.w};
    float bv[4]={xv.x+wv.x,xv.y+wv.y,xv.z+wv.z,xv.w+wv.w};
    float sa=0,sa2=0,sb=0,sb2=0;
    #pragma unroll
    for (int c=0;c<4;c++){ sa+=a[c];sa2+=a[c]*a[c];sb+=bv[c];sb2+=bv[c]*bv[c]; }
    #pragma unroll
    for (int o=16;o;o>>=1){
        sa+=__shfl_xor_sync(~0u,sa,o); sa2+=__shfl_xor_sync(~0u,sa2,o);
        sb+=__shfl_xor_sync(~0u,sb,o); sb2+=__shfl_xor_sync(~0u,sb2,o);
    }
    int w=tid>>5;
    if ((tid&31)==0){ red[0][w]=sa;red[1][w]=sa2;red[2][w]=sb;red[3][w]=sb2; }
    __syncthreads();
    float Sa=red[0][0]+red[0][1]+red[0][2]+red[0][3];
    float Sa2=red[1][0]+red[1][1]+red[1][2]+red[1][3];
    float Sb=red[2][0]+red[2][1]+red[2][2]+red[2][3];
    float Sb2=red[3][0]+red[3][1]+red[3][2]+red[3][3];
    float mua=Sa*(1.f/DM), mub=Sb*(1.f/DM);
    float ra=rsqrtf(Sa2*(1.f/DM)-mua*mua+1e-5f);
    float rb=rsqrtf(Sb2*(1.f/DM)-mub*mub+1e-5f);
    float4 o4; float* op=(float*)&o4;
    #pragma unroll
    for (int c=0;c<4;c++){
        int j=(tid<<2)+c;
        op[c]=(a[c]-mua)*ra*g1[j]+b1[j]+(bv[c]-mub)*rb*g2[j]+b2[j];
    }
    ((float4*)(g_res+(size_t)t*DM))[tid]=o4;
}

// ---------------- LN3 on 2*(ff0+ff1+b2) -> output ----------------
__global__ void ln3_k(const float* __restrict__ fb2, const float* __restrict__ g3,
                      const float* __restrict__ b3, float* __restrict__ out)
{
    __shared__ float red[2][4];
    int t=blockIdx.x, tid=threadIdx.x;
    float4 f0=((const float4*)(g_ff[0]+(size_t)t*DM))[tid];
    float4 f1=((const float4*)(g_ff[1]+(size_t)t*DM))[tid];
    float4 bb=((const float4*)fb2)[tid];
    float v[4]={2.f*(f0.x+f1.x+bb.x),2.f*(f0.y+f1.y+bb.y),2.f*(f0.z+f1.z+bb.z),2.f*(f0.w+f1.w+bb.w)};
    float s=0,s2=0;
    #pragma unroll
    for (int c=0;c<4;c++){ s+=v[c]; s2+=v[c]*v[c]; }
    #pragma unroll
    for (int o=16;o;o>>=1){ s+=__shfl_xor_sync(~0u,s,o); s2+=__shfl_xor_sync(~0u,s2,o); }
    int w=tid>>5;
    if ((tid&31)==0){ red[0][w]=s; red[1][w]=s2; }
    __syncthreads();
    float S=red[0][0]+red[0][1]+red[0][2]+red[0][3];
    float S2=red[1][0]+red[1][1]+red[1][2]+red[1][3];
    float mu=S*(1.f/DM), r=rsqrtf(S2*(1.f/DM)-mu*mu+1e-5f);
    float4 o4; float* op=(float*)&o4;
    #pragma unroll
    for (int c=0;c<4;c++){ int j=(tid<<2)+c; op[c]=(v[c]-mu)*r*g3[j]+b3[j]; }
    ((float4*)(out+(size_t)t*DM))[tid]=o4;
}

// ---------------- launch ----------------
extern "C" void kernel_launch(void* const* d_in, const int* in_sizes, int n_in,
                              void* d_out, int out_size)
{
    const float* x = (const float*)d_in[0];
    const float* inW[2]    = {(const float*)d_in[1],  (const float*)d_in[10]};
    const float* convW[2]  = {(const float*)d_in[2],  (const float*)d_in[11]};
    const float* convB[2]  = {(const float*)d_in[3],  (const float*)d_in[12]};
    const float* xprojW[2] = {(const float*)d_in[4],  (const float*)d_in[13]};
    const float* dtW[2]    = {(const float*)d_in[5],  (const float*)d_in[14]};
    const float* dtB[2]    = {(const float*)d_in[6],  (const float*)d_in[15]};
    const float* Alog[2]   = {(const float*)d_in[7],  (const float*)d_in[16]};
    const float* Dp[2]     = {(const float*)d_in[8],  (const float*)d_in[17]};
    const float* outW[2]   = {(const float*)d_in[9],  (const float*)d_in[18]};
    const float* ln1g=(const float*)d_in[19]; const float* ln1b=(const float*)d_in[20];
    const float* ln2g=(const float*)d_in[21]; const float* ln2b=(const float*)d_in[22];
    const float* ln3g=(const float*)d_in[23]; const float* ln3b=(const float*)d_in[24];
    const float* ffW1=(const float*)d_in[25]; const float* ffb1=(const float*)d_in[26];
    const float* ffW2=(const float*)d_in[27]; const float* ffb2=(const float*)d_in[28];

    float *p_xz, *p_xm, *p_dbc, *p_y, *p_dirout, *p_res, *p_h, *p_ff;
    cudaGetSymbolAddress((void**)&p_xz, g_xz);
    cudaGetSymbolAddress((void**)&p_xm, g_xm);
    cudaGetSymbolAddress((void**)&p_dbc, g_dbc);
    cudaGetSymbolAddress((void**)&p_y, g_y);
    cudaGetSymbolAddress((void**)&p_dirout, g_dirout);
    cudaGetSymbolAddress((void**)&p_res, g_res);
    cudaGetSymbolAddress((void**)&p_h, g_hbuf);
    cudaGetSymbolAddress((void**)&p_ff, g_ff);

    const size_t xzStride=(size_t)TT*2*DI, diStride=(size_t)TT*DI,
                 dbcStride=(size_t)TT*64, dmStride=(size_t)TT*DM;

    const int SMEM = 65536;
    cudaFuncSetAttribute(gemm_tf32, cudaFuncAttributeMaxDynamicSharedMemorySize, SMEM);

    // zero split-K accumulation target (xproj only)
    cudaMemsetAsync(p_dbc, 0, (size_t)2*TT*64*sizeof(float));

    // 1) input projection (both dirs fused; dir1 reads flipped rows)
    {
        GemmArgs a0 = {x, inW[0], nullptr, p_xz,            0, 0};
        GemmArgs a1 = {x, inW[1], nullptr, p_xz + xzStride, 1, 0};
        gemm_tf32<<<dim3((2*DI)/128, TT/128, 2), 512, SMEM>>>(a0, a1, TT, 2*DI, DM, DM, DM, 2*DI, 0, 1);
    }

    // 2) depthwise causal conv + silu (4 timesteps per thread)
    conv_silu_k<<<dim3((unsigned)((size_t)TT*DI/4/256), 2), 256>>>(
        convW[0], convB[0], convW[1], convB[1]);

    // 3) dbc = xm @ xproj^T   (split-K=8, both dirs -> z=16, atomics)
    {
        GemmArgs a0 = {p_xm,          xprojW[0], nullptr, p_dbc};
        GemmArgs a1 = {p_xm+diStride, xprojW[1], nullptr, p_dbc+dbcStride};
        gemm_tf32<<<dim3(1, TT/128, 16), 512, SMEM>>>(a0, a1, TT, 64, DI, DI, DI, 64, 0, 8);
    }

    // 4) chunked selective scan (delta fused from dt rows)
    scanA_k<<<dim3(DI/256, NC, 2*NBATCH), 256>>>(Alog[0], Alog[1], dtW[0], dtW[1], dtB[0], dtB[1]);
    scanB_k<<<(2*NBATCH*DI*DS)/256, 256>>>();
    scanC_k<<<dim3(DI/256, NC, 2*NBATCH), 256>>>(Alog[0], Alog[1], Dp[0], Dp[1],
                                                  dtW[0], dtW[1], dtB[0], dtB[1]);

    // 5) output projection (dir1 writes flipped rows)
    {
        GemmArgs a0 = {p_y,          outW[0], nullptr, p_dirout,          0, 0};
        GemmArgs a1 = {p_y+diStride, outW[1], nullptr, p_dirout+dmStride, 0, 1};
        gemm_tf32<<<dim3(DM/128, TT/128, 2), 512, SMEM>>>(a0, a1, TT, DM, DI, DI, DI, DM, 0, 1);
    }

    // 6) an1 + an2
    ln12_k<<<TT, 128>>>(x, ln1g, ln1b, ln2g, ln2b);

    // 7) FFN
    {
        GemmArgs a0 = {p_res, ffW1, ffb1, p_h, 0, 0};
        gemm_tf32<<<dim3(DFF/128, TT/128, 1), 512, SMEM>>>(a0, a0, TT, DFF, DM, DM, DM, DFF, 1, 1);
    }
    {
        // split-K=2 via pointer-offset halves into two disjoint buffers (no atomics)
        GemmArgs a0 = {p_h,         ffW2,         nullptr, p_ff,          0, 0};
        GemmArgs a1 = {p_h + DFF/2, ffW2 + DFF/2, nullptr, p_ff+dmStride, 0, 0};
        gemm_tf32<<<dim3(DM/128, TT/128, 2), 512, SMEM>>>(a0, a1, TT, DM, DFF/2, DFF, DFF, DM, 0, 1);
    }

    // 8) LN(2*(ff0+ff1+b2)) -> output
    ln3_k<<<TT, 128>>>(ffb2, ln3g, ln3b, (float*)d_out);
}

// round 15
// speedup vs baseline: 1.5307x; 1.5307x over previous
#include <cuda_runtime.h>
#include <math.h>

// ---------------- problem constants ----------------
#define LSEQ   1024
#define NBATCH 2
#define TT     (NBATCH*LSEQ)   // 2048 tokens
#define DM     512
#define DI     1024
#define DFF    2048
#define DS     16
#define DTR    32
#define NC     32              // scan chunks
#define LC     (LSEQ/NC)       // 32 steps per chunk
#define TCH    64              // delta_k t-chunk

// ---------------- scratch ----------------
__device__ float g_xz[2][(size_t)TT*2*DI];
__device__ float g_xm[2][(size_t)TT*DI];
__device__ float g_dbc[2][(size_t)TT*64];
__device__ float g_delta[2][(size_t)TT*DI];
__device__ float g_y[2][(size_t)TT*DI];
__device__ float g_dirout[2][(size_t)TT*DM];
__device__ float g_res[(size_t)TT*DM];
__device__ float g_hbuf[(size_t)TT*DFF];
__device__ float g_ff[2][(size_t)TT*DM];      // two split-K partial buffers
__device__ float g_P [(size_t)2*NBATCH*NC*DS*DI];
__device__ float g_q [(size_t)2*NBATCH*NC*DS*DI];
__device__ float g_h0[(size_t)2*NBATCH*NC*DS*DI];

// ---------------- TF32 tensor-core GEMM ----------------
// C[M,N] = A[M,K] * W[N,K]^T ; A row-major (lda), W row-major (ldb).
// CTA tile 128x128xKT32, 512 threads, 16 warps of 32x32 warp tiles.
// SMEM in MMA-fragment-interleaved layout, XOR bank swizzle; frag loads are
// 1x LDS.128 (A) / 1x LDS.64 (B), conflict-free.
struct GemmArgs { const float* A; const float* W; const float* bias; float* C; int flipA; int flipC; };

#define KT 32

__device__ __forceinline__ unsigned f2tf32(float f) {
    unsigned u; asm("cvt.rna.tf32.f32 %0, %1;" : "=r"(u) : "f"(f)); return u;
}
__device__ __forceinline__ float cvtf(float f) { return __uint_as_float(f2tf32(f)); }

__global__ __launch_bounds__(512,1) void gemm_tf32(
    GemmArgs ga0, GemmArgs ga1, int M, int N, int K, int lda, int ldb, int ldc, int mode, int S)
{
    extern __shared__ float sh[];
    float* shA = sh; float* shB = sh + 8192;
    const int z = blockIdx.z;
    const int dir = z / S, sk = z - dir*S;
    const GemmArgs g = dir ? ga1 : ga0;
    const int kLen = K/S, kOff = sk*kLen;
    const int tid = threadIdx.x, lane = tid&31, w = tid>>5;
    const int gq = lane>>2, tq = lane&3;
    const int wm = (w&3)*32, wn = (w>>2)*32;
    const int wgm = (w&3)*2, wgn = (w>>2)*4;
    const int m0 = blockIdx.y*128, n0 = blockIdx.x*128;
    const int lr = tid>>3, lc4 = (tid&7)*4;
    const int ksl = lc4>>3, khalf = (lc4>>2)&1;

    size_t aRow[2], bRow[2];
    #pragma unroll
    for (int i=0;i<2;i++){
        int m = m0+lr+i*64;
        int r = m;
        if (g.flipA) r = (m&~(LSEQ-1)) + (LSEQ-1 - (m&(LSEQ-1)));
        aRow[i] = (size_t)r*lda + kOff;
    }
    #pragma unroll
    for (int i=0;i<2;i++){ int n=n0+lr+i*64; if(n>=N)n=N-1; bRow[i]=(size_t)n*ldb+kOff; }
    int aBase[2], bBase[2];
    #pragma unroll
    for (int i=0;i<2;i++){
        int m=lr+i*64; int gg=m>>4, gq_=m&7, mh=(m>>3)&1;
        aBase[i]=((((gg*4+ksl)*8+gq_)<<4))+khalf*2+mh;
        int gb=m>>3, gqb=m&7;
        bBase[i]=((((gb*4+ksl)*8+gqb)<<3))+khalf;
    }
    float4 aReg[2], bReg[2];
    #pragma unroll
    for (int i=0;i<2;i++) aReg[i]=*(const float4*)(g.A+aRow[i]+lc4);
    #pragma unroll
    for (int i=0;i<2;i++) bReg[i]=*(const float4*)(g.W+bRow[i]+lc4);
    float c[2][4][4];
    #pragma unroll
    for (int mt=0;mt<2;mt++) for (int nt=0;nt<4;nt++) for (int r=0;r<4;r++) c[mt][nt][r]=0.f;
    int buf=0;
    #pragma unroll
    for (int i=0;i<2;i++){
        float* p=shA+aBase[i]; float v[4]={aReg[i].x,aReg[i].y,aReg[i].z,aReg[i].w};
        #pragma unroll
        for(int j=0;j<4;j++) p[(j^ksl)<<2]=cvtf(v[j]);
        float* q=shB+bBase[i]; float u[4]={bReg[i].x,bReg[i].y,bReg[i].z,bReg[i].w};
        #pragma unroll
        for(int j=0;j<4;j++) q[(j^ksl)<<1]=cvtf(u[j]);
    }
    __syncthreads();
    for (int kt=0; kt<kLen; kt+=KT){
        bool more = (kt+KT)<kLen;
        if (more){
            #pragma unroll
            for (int i=0;i<2;i++) aReg[i]=*(const float4*)(g.A+aRow[i]+kt+KT+lc4);
            #pragma unroll
            for (int i=0;i<2;i++) bReg[i]=*(const float4*)(g.W+bRow[i]+kt+KT+lc4);
        }
        const float4* Ap=(const float4*)(shA+buf*4096);
        const float2* Bp=(const float2*)(shB+buf*4096);
        #pragma unroll
        for (int ks=0;ks<4;ks++){
            const int tqp=tq^ks;
            float4 av[2]; float2 bv[4];
            #pragma unroll
            for (int mt=0;mt<2;mt++) av[mt]=Ap[(((wgm+mt)*4+ks)*8+gq)*4+tqp];
            #pragma unroll
            for (int nt=0;nt<4;nt++) bv[nt]=Bp[(((wgn+nt)*4+ks)*8+gq)*4+tqp];
            #pragma unroll
            for (int mt=0;mt<2;mt++)
                #pragma unroll
                for (int nt=0;nt<4;nt++)
                    asm volatile("mma.sync.aligned.m16n8k8.row.col.f32.tf32.tf32.f32 {%0,%1,%2,%3}, {%4,%5,%6,%7}, {%8,%9}, {%0,%1,%2,%3};"
                        : "+f"(c[mt][nt][0]),"+f"(c[mt][nt][1]),"+f"(c[mt][nt][2]),"+f"(c[mt][nt][3])
                        : "r"(__float_as_uint(av[mt].x)),"r"(__float_as_uint(av[mt].y)),
                          "r"(__float_as_uint(av[mt].z)),"r"(__float_as_uint(av[mt].w)),
                          "r"(__float_as_uint(bv[nt].x)),"r"(__float_as_uint(bv[nt].y)));
        }
        if (more){
            int nb=buf^1;
            #pragma unroll
            for (int i=0;i<2;i++){
                float* p=shA+nb*4096+aBase[i]; float v[4]={aReg[i].x,aReg[i].y,aReg[i].z,aReg[i].w};
                #pragma unroll
                for(int j=0;j<4;j++) p[(j^ksl)<<2]=cvtf(v[j]);
                float* q=shB+nb*4096+bBase[i]; float u[4]={bReg[i].x,bReg[i].y,bReg[i].z,bReg[i].w};
                #pragma unroll
                for(int j=0;j<4;j++) q[(j^ksl)<<1]=cvtf(u[j]);
            }
        }
        __syncthreads();
        buf^=1;
    }
    #pragma unroll
    for (int mt=0;mt<2;mt++)
        #pragma unroll
        for (int half=0;half<2;half++){
            int m = m0 + wm + mt*16 + gq + half*8;
            int orow = m;
            if (g.flipC) orow = (m&~(LSEQ-1)) + (LSEQ-1 - (m&(LSEQ-1)));
            #pragma unroll
            for (int nt=0;nt<4;nt++){
                int col = n0 + wn + nt*8 + 2*tq;
                if (col>=N) continue;
                float v0=c[mt][nt][half*2+0], v1=c[mt][nt][half*2+1];
                if (S>1){
                    atomicAdd(g.C+(size_t)orow*ldc+col, v0);
                    atomicAdd(g.C+(size_t)orow*ldc+col+1, v1);
                } else {
                    if (mode){ v0+=g.bias[col]; v1+=g.bias[col+1]; }
                    if (mode==1){ v0=fmaxf(v0,0.f); v1=fmaxf(v1,0.f); }
                    *(float2*)(g.C+(size_t)orow*ldc+col)=make_float2(v0,v1);
                }
            }
        }
}

// ---------------- causal depthwise conv (width 4) + silu, 4 t per thread ----------------
__global__ void conv_silu_k(const float* __restrict__ fW, const float* __restrict__ fb,
                            const float* __restrict__ bW, const float* __restrict__ bb)
{
    int dir = blockIdx.y;
    size_t idx = (size_t)blockIdx.x*blockDim.x + threadIdx.x;   // over TT*DI/4
    int e  = (int)(idx % DI);
    int tg = (int)(idx / DI);
    int t0 = tg*4;
    int l0 = t0 & (LSEQ-1);
    const float* cw = dir ? bW : fW;
    const float* cb = dir ? bb : fb;
    const float* xz = g_xz[dir];
    float w0=cw[e*4+0], w1=cw[e*4+1], w2=cw[e*4+2], w3=cw[e*4+3];
    float bias = cb[e];
    float v[7];
    #pragma unroll
    for (int k = 0; k < 7; k++) {
        int off = k - 3;                 // input t offset -3..+3
        v[k] = (l0 + off >= 0) ? xz[(size_t)(t0+off)*(2*DI) + e] : 0.f;
    }
    float* xm = g_xm[dir];
    #pragma unroll
    for (int j = 0; j < 4; j++) {
        float acc = bias + v[j]*w0 + v[j+1]*w1 + v[j+2]*w2 + v[j+3]*w3;
        xm[(size_t)(t0+j)*DI + e] = acc / (1.f + __expf(-acc));
    }
}

// ---------------- delta: softplus(dt-row . dtW[e] + dtb) with smem-staged dt rows ----------------
__global__ __launch_bounds__(256) void delta_k(
    const float* __restrict__ fdtW, const float* __restrict__ bdtW,
    const float* __restrict__ fdtB, const float* __restrict__ bdtB)
{
    __shared__ float sdt[TCH][DTR];      // 64 x 32 = 8 KB
    int dir = blockIdx.z;
    int e   = blockIdx.x*256 + threadIdx.x;
    int t0  = blockIdx.y*TCH;
    const float* dtW = dir ? bdtW : fdtW;
    const float  dtb = (dir ? bdtB : fdtB)[e];
    const float* dbc = g_dbc[dir];
    float* delta = g_delta[dir];

    float wr[32];
    {
        const float4* W4 = (const float4*)(dtW + (size_t)e*DTR);
        #pragma unroll
        for (int j=0;j<8;j++){ float4 v=W4[j]; wr[j*4]=v.x;wr[j*4+1]=v.y;wr[j*4+2]=v.z;wr[j*4+3]=v.w; }
    }
    // stage TCH dt rows (coalesced: dbc row stride 64, dt is first 32)
    for (int i = threadIdx.x; i < TCH*DTR; i += 256) {
        int tt = i >> 5, k = i & 31;
        sdt[tt][k] = dbc[(size_t)(t0+tt)*64 + k];
    }
    __syncthreads();
    for (int j = 0; j < TCH; j++) {
        const float4* R = (const float4*)sdt[j];
        float dot = dtb;
        #pragma unroll
        for (int q=0;q<8;q++){
            float4 v = R[q];
            dot += v.x*wr[q*4+0] + v.y*wr[q*4+1] + v.z*wr[q*4+2] + v.w*wr[q*4+3];
        }
        delta[(size_t)(t0+j)*DI + e] = (dot > 20.f) ? dot : __logf(1.f + __expf(dot));
    }
}

// ---------------- scan helpers ----------------
__device__ __forceinline__ void load_negA(const float* Alog, int e, float* negA, bool& fast){
    const float4* Ar = (const float4*)(Alog + (size_t)e*16);
    #pragma unroll
    for (int s4=0;s4<4;s4++){
        float4 v=Ar[s4];
        negA[s4*4+0]=-__expf(v.x); negA[s4*4+1]=-__expf(v.y);
        negA[s4*4+2]=-__expf(v.z); negA[s4*4+3]=-__expf(v.w);
    }
    fast = true;
    #pragma unroll
    for (int s=0;s<16;s++) fast = fast && (fabsf(negA[s]+(float)(s+1)) <= 1e-3f*(float)(s+1));
}
__device__ __forceinline__ void comp_dA(float d, const float* negA, bool fast, float* da){
    if (fast){ float r=__expf(-d); da[0]=r;
        #pragma unroll
        for (int s=1;s<16;s++) da[s]=da[s-1]*r;
    } else {
        #pragma unroll
        for (int s=0;s<16;s++) da[s]=__expf(d*negA[s]);
    }
}

// ---------------- scan phase A ----------------
__global__ __launch_bounds__(256) void scanA_k(const float* __restrict__ fA, const float* __restrict__ bA)
{
    int e = blockIdx.x*256+threadIdx.x, c = blockIdx.y;
    int dir = blockIdx.z>>1, b = blockIdx.z&1;
    const float* Alog = dir?bA:fA;
    const float* delta = g_delta[dir]; const float* xm = g_xm[dir]; const float* dbc = g_dbc[dir];
    float negA[16]; bool fast; load_negA(Alog,e,negA,fast);
    float P[16], q[16];
    #pragma unroll
    for (int s=0;s<16;s++){ P[s]=1.f; q[s]=0.f; }
    int l0=c*LC;
    for (int l=l0;l<l0+LC;l++){
        int t=(b<<10)+l; size_t te=(size_t)t*DI+e;
        float d=delta[te], xv=xm[te], dx=d*xv;
        const float4* Bv=(const float4*)(dbc+(size_t)t*64+32);
        float Bsx[16];
        #pragma unroll
        for (int s4=0;s4<4;s4++){ float4 v=Bv[s4]; Bsx[s4*4]=v.x;Bsx[s4*4+1]=v.y;Bsx[s4*4+2]=v.z;Bsx[s4*4+3]=v.w; }
        float da[16]; comp_dA(d,negA,fast,da);
        #pragma unroll
        for (int s=0;s<16;s++){ q[s]=da[s]*q[s]+dx*Bsx[s]; P[s]*=da[s]; }
    }
    size_t base=(((size_t)(dir*2+b)*NC+c)*16)*DI+e;
    #pragma unroll
    for (int s=0;s<16;s++){ g_P[base+(size_t)s*DI]=P[s]; g_q[base+(size_t)s*DI]=q[s]; }
}

// ---------------- scan phase B ----------------
__global__ void scanB_k(){
    int idx = blockIdx.x*256+threadIdx.x;
    int e=idx&(DI-1), s=(idx>>10)&15, cb=idx>>14;
    float h=0.f;
    #pragma unroll 4
    for (int c=0;c<NC;c++){
        size_t base=(((size_t)cb*NC+c)*16+s)*DI+e;
        g_h0[base]=h; h=g_P[base]*h+g_q[base];
    }
}

// ---------------- scan phase C ----------------
__global__ __launch_bounds__(256) void scanC_k(const float* __restrict__ fA, const float* __restrict__ bA,
                                               const float* __restrict__ fD, const float* __restrict__ bD)
{
    int e = blockIdx.x*256+threadIdx.x, c = blockIdx.y;
    int dir = blockIdx.z>>1, b = blockIdx.z&1;
    const float* Alog = dir?bA:fA; const float* Dp = dir?bD:fD;
    const float* delta = g_delta[dir]; const float* xm = g_xm[dir];
    const float* dbc = g_dbc[dir]; const float* xz = g_xz[dir];
    float* yout = g_y[dir];
    float negA[16]; bool fast; load_negA(Alog,e,negA,fast);
    float h[16];
    size_t hb=(((size_t)(dir*2+b)*NC+c)*16)*DI+e;
    #pragma unroll
    for (int s=0;s<16;s++) h[s]=g_h0[hb+(size_t)s*DI];
    float Dpe=Dp[e];
    int l0=c*LC;
    for (int l=l0;l<l0+LC;l++){
        int t=(b<<10)+l; size_t te=(size_t)t*DI+e;
        float d=delta[te], xv=xm[te], dx=d*xv;
        const float4* BCv=(const float4*)(dbc+(size_t)t*64+32);
        float Bsx[16], Cs[16];
        #pragma unroll
        for (int s4=0;s4<4;s4++){
            float4 v=BCv[s4];   Bsx[s4*4]=v.x;Bsx[s4*4+1]=v.y;Bsx[s4*4+2]=v.z;Bsx[s4*4+3]=v.w;
            float4 w=BCv[4+s4]; Cs[s4*4]=w.x;Cs[s4*4+1]=w.y;Cs[s4*4+2]=w.z;Cs[s4*4+3]=w.w;
        }
        float da[16]; comp_dA(d,negA,fast,da);
        float y=0.f;
        #pragma unroll
        for (int s=0;s<16;s++){ h[s]=da[s]*h[s]+dx*Bsx[s]; y+=h[s]*Cs[s]; }
        float zv=xz[(size_t)t*(2*DI)+DI+e];
        float sil=zv/(1.f+__expf(-zv));
        yout[te]=(y+xv*Dpe)*sil;
    }
}

// ---------------- LN1 + LN2 + sum ----------------
__global__ void ln12_k(const float* __restrict__ x,
                       const float* __restrict__ g1, const float* __restrict__ b1,
                       const float* __restrict__ g2, const float* __restrict__ b2)
{
    __shared__ float red[4][4];
    int t=blockIdx.x, tid=threadIdx.x;
    float4 xv=((const float4*)(x+(size_t)t*DM))[tid];
    float4 fv=((const float4*)(g_dirout[0]+(size_t)t*DM))[tid];
    float4 wv=((const float4*)(g_dirout[1]+(size_t)t*DM))[tid];
    float a[4]={xv.x+fv.x,xv.y+fv.y,xv.z+fv.z,xv.w+fv.w};
    float bv[4]={xv.x+wv.x,xv.y+wv.y,xv.z+wv.z,xv.w+wv.w};
    float sa=0,sa2=0,sb=0,sb2=0;
    #pragma unroll
    for (int c=0;c<4;c++){ sa+=a[c];sa2+=a[c]*a[c];sb+=bv[c];sb2+=bv[c]*bv[c]; }
    #pragma unroll
    for (int o=16;o;o>>=1){
        sa+=__shfl_xor_sync(~0u,sa,o); sa2+=__shfl_xor_sync(~0u,sa2,o);
        sb+=__shfl_xor_sync(~0u,sb,o); sb2+=__shfl_xor_sync(~0u,sb2,o);
    }
    int w=tid>>5;
    if ((tid&31)==0){ red[0][w]=sa;red[1][w]=sa2;red[2][w]=sb;red[3][w]=sb2; }
    __syncthreads();
    float Sa=red[0][0]+red[0][1]+red[0][2]+red[0][3];
    float Sa2=red[1][0]+red[1][1]+red[1][2]+red[1][3];
    float Sb=red[2][0]+red[2][1]+red[2][2]+red[2][3];
    float Sb2=red[3][0]+red[3][1]+red[3][2]+red[3][3];
    float mua=Sa*(1.f/DM), mub=Sb*(1.f/DM);
    float ra=rsqrtf(Sa2*(1.f/DM)-mua*mua+1e-5f);
    float rb=rsqrtf(Sb2*(1.f/DM)-mub*mub+1e-5f);
    float4 o4; float* op=(float*)&o4;
    #pragma unroll
    for (int c=0;c<4;c++){
        int j=(tid<<2)+c;
        op[c]=(a[c]-mua)*ra*g1[j]+b1[j]+(bv[c]-mub)*rb*g2[j]+b2[j];
    }
    ((float4*)(g_res+(size_t)t*DM))[tid]=o4;
}

// ---------------- LN3 on 2*(ff0+ff1+b2) -> output ----------------
__global__ void ln3_k(const float* __restrict__ fb2, const float* __restrict__ g3,
                      const float* __restrict__ b3, float* __restrict__ out)
{
    __shared__ float red[2][4];
    int t=blockIdx.x, tid=threadIdx.x;
    float4 f0=((const float4*)(g_ff[0]+(size_t)t*DM))[tid];
    float4 f1=((const float4*)(g_ff[1]+(size_t)t*DM))[tid];
    float4 bb=((const float4*)fb2)[tid];
    float v[4]={2.f*(f0.x+f1.x+bb.x),2.f*(f0.y+f1.y+bb.y),2.f*(f0.z+f1.z+bb.z),2.f*(f0.w+f1.w+bb.w)};
    float s=0,s2=0;
    #pragma unroll
    for (int c=0;c<4;c++){ s+=v[c]; s2+=v[c]*v[c]; }
    #pragma unroll
    for (int o=16;o;o>>=1){ s+=__shfl_xor_sync(~0u,s,o); s2+=__shfl_xor_sync(~0u,s2,o); }
    int w=tid>>5;
    if ((tid&31)==0){ red[0][w]=s; red[1][w]=s2; }
    __syncthreads();
    float S=red[0][0]+red[0][1]+red[0][2]+red[0][3];
    float S2=red[1][0]+red[1][1]+red[1][2]+red[1][3];
    float mu=S*(1.f/DM), r=rsqrtf(S2*(1.f/DM)-mu*mu+1e-5f);
    float4 o4; float* op=(float*)&o4;
    #pragma unroll
    for (int c=0;c<4;c++){ int j=(tid<<2)+c; op[c]=(v[c]-mu)*r*g3[j]+b3[j]; }
    ((float4*)(out+(size_t)t*DM))[tid]=o4;
}

// ---------------- launch ----------------
extern "C" void kernel_launch(void* const* d_in, const int* in_sizes, int n_in,
                              void* d_out, int out_size)
{
    const float* x = (const float*)d_in[0];
    const float* inW[2]    = {(const float*)d_in[1],  (const float*)d_in[10]};
    const float* convW[2]  = {(const float*)d_in[2],  (const float*)d_in[11]};
    const float* convB[2]  = {(const float*)d_in[3],  (const float*)d_in[12]};
    const float* xprojW[2] = {(const float*)d_in[4],  (const float*)d_in[13]};
    const float* dtW[2]    = {(const float*)d_in[5],  (const float*)d_in[14]};
    const float* dtB[2]    = {(const float*)d_in[6],  (const float*)d_in[15]};
    const float* Alog[2]   = {(const float*)d_in[7],  (const float*)d_in[16]};
    const float* Dp[2]     = {(const float*)d_in[8],  (const float*)d_in[17]};
    const float* outW[2]   = {(const float*)d_in[9],  (const float*)d_in[18]};
    const float* ln1g=(const float*)d_in[19]; const float* ln1b=(const float*)d_in[20];
    const float* ln2g=(const float*)d_in[21]; const float* ln2b=(const float*)d_in[22];
    const float* ln3g=(const float*)d_in[23]; const float* ln3b=(const float*)d_in[24];
    const float* ffW1=(const float*)d_in[25]; const float* ffb1=(const float*)d_in[26];
    const float* ffW2=(const float*)d_in[27]; const float* ffb2=(const float*)d_in[28];

    float *p_xz, *p_xm, *p_dbc, *p_y, *p_dirout, *p_res, *p_h, *p_ff;
    cudaGetSymbolAddress((void**)&p_xz, g_xz);
    cudaGetSymbolAddress((void**)&p_xm, g_xm);
    cudaGetSymbolAddress((void**)&p_dbc, g_dbc);
    cudaGetSymbolAddress((void**)&p_y, g_y);
    cudaGetSymbolAddress((void**)&p_dirout, g_dirout);
    cudaGetSymbolAddress((void**)&p_res, g_res);
    cudaGetSymbolAddress((void**)&p_h, g_hbuf);
    cudaGetSymbolAddress((void**)&p_ff, g_ff);

    const size_t xzStride=(size_t)TT*2*DI, diStride=(size_t)TT*DI,
                 dbcStride=(size_t)TT*64, dmStride=(size_t)TT*DM;

    const int SMEM = 65536;
    cudaFuncSetAttribute(gemm_tf32, cudaFuncAttributeMaxDynamicSharedMemorySize, SMEM);

    // zero split-K accumulation target (xproj only)
    cudaMemsetAsync(p_dbc, 0, (size_t)2*TT*64*sizeof(float));

    // 1) input projection (both dirs fused; dir1 reads flipped rows)
    {
        GemmArgs a0 = {x, inW[0], nullptr, p_xz,            0, 0};
        GemmArgs a1 = {x, inW[1], nullptr, p_xz + xzStride, 1, 0};
        gemm_tf32<<<dim3((2*DI)/128, TT/128, 2), 512, SMEM>>>(a0, a1, TT, 2*DI, DM, DM, DM, 2*DI, 0, 1);
    }

    // 2) depthwise causal conv + silu (4 timesteps per thread)
    conv_silu_k<<<dim3((unsigned)((size_t)TT*DI/4/256), 2), 256>>>(
        convW[0], convB[0], convW[1], convB[1]);

    // 3a) dbc = xm @ xproj^T   (split-K=8, both dirs -> z=16, atomics)
    {
        GemmArgs a0 = {p_xm,          xprojW[0], nullptr, p_dbc};
        GemmArgs a1 = {p_xm+diStride, xprojW[1], nullptr, p_dbc+dbcStride};
        gemm_tf32<<<dim3(1, TT/128, 16), 512, SMEM>>>(a0, a1, TT, 64, DI, DI, DI, 64, 0, 8);
    }
    // 3b) delta = softplus(dt @ dtW^T + dtb)  — SIMT, smem-staged dt rows
    delta_k<<<dim3(DI/256, TT/TCH, 2), 256>>>(dtW[0], dtW[1], dtB[0], dtB[1]);

    // 4) chunked selective scan
    scanA_k<<<dim3(DI/256, NC, 2*NBATCH), 256>>>(Alog[0], Alog[1]);
    scanB_k<<<(2*NBATCH*DI*DS)/256, 256>>>();
    scanC_k<<<dim3(DI/256, NC, 2*NBATCH), 256>>>(Alog[0], Alog[1], Dp[0], Dp[1]);

    // 5) output projection (dir1 writes flipped rows)
    {
        GemmArgs a0 = {p_y,          outW[0], nullptr, p_dirout,          0, 0};
        GemmArgs a1 = {p_y+diStride, outW[1], nullptr, p_dirout+dmStride, 0, 1};
        gemm_tf32<<<dim3(DM/128, TT/128, 2), 512, SMEM>>>(a0, a1, TT, DM, DI, DI, DI, DM, 0, 1);
    }

    // 6) an1 + an2
    ln12_k<<<TT, 128>>>(x, ln1g, ln1b, ln2g, ln2b);

    // 7) FFN
    {
        GemmArgs a0 = {p_res, ffW1, ffb1, p_h, 0, 0};
        gemm_tf32<<<dim3(DFF/128, TT/128, 1), 512, SMEM>>>(a0, a0, TT, DFF, DM, DM, DM, DFF, 1, 1);
    }
    {
        // split-K=2 via pointer-offset halves into two disjoint buffers (no atomics)
        GemmArgs a0 = {p_h,         ffW2,         nullptr, p_ff,          0, 0};
        GemmArgs a1 = {p_h + DFF/2, ffW2 + DFF/2, nullptr, p_ff+dmStride, 0, 0};
        gemm_tf32<<<dim3(DM/128, TT/128, 2), 512, SMEM>>>(a0, a1, TT, DM, DFF/2, DFF, DFF, DM, 0, 1);
    }

    // 8) LN(2*(ff0+ff1+b2)) -> output
    ln3_k<<<TT, 128>>>(ffb2, ln3g, ln3b, (float*)d_out);
}

// round 16
// speedup vs baseline: 1.5402x; 1.0062x over previous
#include <cuda_runtime.h>
#include <math.h>

// ---------------- problem constants ----------------
#define LSEQ   1024
#define NBATCH 2
#define TT     (NBATCH*LSEQ)   // 2048 tokens
#define DM     512
#define DI     1024
#define DFF    2048
#define DS     16
#define DTR    32
#define NC     32              // scan chunks
#define LC     (LSEQ/NC)       // 32 steps per chunk
#define TCH    64              // delta_k t-chunk

// ---------------- scratch ----------------
__device__ float g_xz[2][(size_t)TT*2*DI];
__device__ float g_xm[2][(size_t)TT*DI];
__device__ float g_dbc[2][(size_t)TT*64];
__device__ float g_delta[2][(size_t)TT*DI];
__device__ float g_y[2][(size_t)TT*DI];
__device__ float g_dirout[2][(size_t)TT*DM];
__device__ float g_res[(size_t)TT*DM];
__device__ float g_hbuf[(size_t)TT*DFF];
__device__ float g_ff[2][(size_t)TT*DM];      // two split-K partial buffers
__device__ float g_P [(size_t)2*NBATCH*NC*DS*DI];
__device__ float g_q [(size_t)2*NBATCH*NC*DS*DI];
__device__ float g_h0[(size_t)2*NBATCH*NC*DS*DI];

// ---------------- TF32 tensor-core GEMM ----------------
// C[M,N] = A[M,K] * W[N,K]^T ; A row-major (lda), W row-major (ldb).
// CTA tile 128x128xKT32, 512 threads, 16 warps of 32x32 warp tiles.
// SMEM in MMA-fragment-interleaved layout, XOR bank swizzle; frag loads are
// 1x LDS.128 (A) / 1x LDS.64 (B), conflict-free.
struct GemmArgs { const float* A; const float* W; const float* bias; float* C; int flipA; int flipC; };

#define KT 32

__device__ __forceinline__ unsigned f2tf32(float f) {
    unsigned u; asm("cvt.rna.tf32.f32 %0, %1;" : "=r"(u) : "f"(f)); return u;
}
__device__ __forceinline__ float cvtf(float f) { return __uint_as_float(f2tf32(f)); }

__global__ __launch_bounds__(512,1) void gemm_tf32(
    GemmArgs ga0, GemmArgs ga1, int M, int N, int K, int lda, int ldb, int ldc, int mode, int S)
{
    extern __shared__ float sh[];
    float* shA = sh; float* shB = sh + 8192;
    const int z = blockIdx.z;
    const int dir = z / S, sk = z - dir*S;
    const GemmArgs g = dir ? ga1 : ga0;
    const int kLen = K/S, kOff = sk*kLen;
    const int tid = threadIdx.x, lane = tid&31, w = tid>>5;
    const int gq = lane>>2, tq = lane&3;
    const int wm = (w&3)*32, wn = (w>>2)*32;
    const int wgm = (w&3)*2, wgn = (w>>2)*4;
    const int m0 = blockIdx.y*128, n0 = blockIdx.x*128;
    const int lr = tid>>3, lc4 = (tid&7)*4;
    const int ksl = lc4>>3, khalf = (lc4>>2)&1;

    size_t aRow[2], bRow[2];
    #pragma unroll
    for (int i=0;i<2;i++){
        int m = m0+lr+i*64;
        int r = m;
        if (g.flipA) r = (m&~(LSEQ-1)) + (LSEQ-1 - (m&(LSEQ-1)));
        aRow[i] = (size_t)r*lda + kOff;
    }
    #pragma unroll
    for (int i=0;i<2;i++){ int n=n0+lr+i*64; if(n>=N)n=N-1; bRow[i]=(size_t)n*ldb+kOff; }
    int aBase[2], bBase[2];
    #pragma unroll
    for (int i=0;i<2;i++){
        int m=lr+i*64; int gg=m>>4, gq_=m&7, mh=(m>>3)&1;
        aBase[i]=((((gg*4+ksl)*8+gq_)<<4))+khalf*2+mh;
        int gb=m>>3, gqb=m&7;
        bBase[i]=((((gb*4+ksl)*8+gqb)<<3))+khalf;
    }
    float4 aReg[2], bReg[2];
    #pragma unroll
    for (int i=0;i<2;i++) aReg[i]=*(const float4*)(g.A+aRow[i]+lc4);
    #pragma unroll
    for (int i=0;i<2;i++) bReg[i]=*(const float4*)(g.W+bRow[i]+lc4);
    float c[2][4][4];
    #pragma unroll
    for (int mt=0;mt<2;mt++) for (int nt=0;nt<4;nt++) for (int r=0;r<4;r++) c[mt][nt][r]=0.f;
    int buf=0;
    #pragma unroll
    for (int i=0;i<2;i++){
        float* p=shA+aBase[i]; float v[4]={aReg[i].x,aReg[i].y,aReg[i].z,aReg[i].w};
        #pragma unroll
        for(int j=0;j<4;j++) p[(j^ksl)<<2]=cvtf(v[j]);
        float* q=shB+bBase[i]; float u[4]={bReg[i].x,bReg[i].y,bReg[i].z,bReg[i].w};
        #pragma unroll
        for(int j=0;j<4;j++) q[(j^ksl)<<1]=cvtf(u[j]);
    }
    __syncthreads();
    for (int kt=0; kt<kLen; kt+=KT){
        bool more = (kt+KT)<kLen;
        if (more){
            #pragma unroll
            for (int i=0;i<2;i++) aReg[i]=*(const float4*)(g.A+aRow[i]+kt+KT+lc4);
            #pragma unroll
            for (int i=0;i<2;i++) bReg[i]=*(const float4*)(g.W+bRow[i]+kt+KT+lc4);
        }
        const float4* Ap=(const float4*)(shA+buf*4096);
        const float2* Bp=(const float2*)(shB+buf*4096);
        #pragma unroll
        for (int ks=0;ks<4;ks++){
            const int tqp=tq^ks;
            float4 av[2]; float2 bv[4];
            #pragma unroll
            for (int mt=0;mt<2;mt++) av[mt]=Ap[(((wgm+mt)*4+ks)*8+gq)*4+tqp];
            #pragma unroll
            for (int nt=0;nt<4;nt++) bv[nt]=Bp[(((wgn+nt)*4+ks)*8+gq)*4+tqp];
            #pragma unroll
            for (int mt=0;mt<2;mt++)
                #pragma unroll
                for (int nt=0;nt<4;nt++)
                    asm volatile("mma.sync.aligned.m16n8k8.row.col.f32.tf32.tf32.f32 {%0,%1,%2,%3}, {%4,%5,%6,%7}, {%8,%9}, {%0,%1,%2,%3};"
                        : "+f"(c[mt][nt][0]),"+f"(c[mt][nt][1]),"+f"(c[mt][nt][2]),"+f"(c[mt][nt][3])
                        : "r"(__float_as_uint(av[mt].x)),"r"(__float_as_uint(av[mt].y)),
                          "r"(__float_as_uint(av[mt].z)),"r"(__float_as_uint(av[mt].w)),
                          "r"(__float_as_uint(bv[nt].x)),"r"(__float_as_uint(bv[nt].y)));
        }
        if (more){
            int nb=buf^1;
            #pragma unroll
            for (int i=0;i<2;i++){
                float* p=shA+nb*4096+aBase[i]; float v[4]={aReg[i].x,aReg[i].y,aReg[i].z,aReg[i].w};
                #pragma unroll
                for(int j=0;j<4;j++) p[(j^ksl)<<2]=cvtf(v[j]);
                float* q=shB+nb*4096+bBase[i]; float u[4]={bReg[i].x,bReg[i].y,bReg[i].z,bReg[i].w};
                #pragma unroll
                for(int j=0;j<4;j++) q[(j^ksl)<<1]=cvtf(u[j]);
            }
        }
        __syncthreads();
        buf^=1;
    }
    #pragma unroll
    for (int mt=0;mt<2;mt++)
        #pragma unroll
        for (int half=0;half<2;half++){
            int m = m0 + wm + mt*16 + gq + half*8;
            int orow = m;
            if (g.flipC) orow = (m&~(LSEQ-1)) + (LSEQ-1 - (m&(LSEQ-1)));
            #pragma unroll
            for (int nt=0;nt<4;nt++){
                int col = n0 + wn + nt*8 + 2*tq;
                if (col>=N) continue;
                float v0=c[mt][nt][half*2+0], v1=c[mt][nt][half*2+1];
                if (S>1){
                    atomicAdd(g.C+(size_t)orow*ldc+col, v0);
                    atomicAdd(g.C+(size_t)orow*ldc+col+1, v1);
                } else {
                    if (mode){ v0+=g.bias[col]; v1+=g.bias[col+1]; }
                    if (mode==1){ v0=fmaxf(v0,0.f); v1=fmaxf(v1,0.f); }
                    *(float2*)(g.C+(size_t)orow*ldc+col)=make_float2(v0,v1);
                }
            }
        }
}

// ---------------- causal depthwise conv (width 4) + silu, 4 t per thread ----------------
__global__ void conv_silu_k(const float* __restrict__ fW, const float* __restrict__ fb,
                            const float* __restrict__ bW, const float* __restrict__ bb)
{
    int dir = blockIdx.y;
    size_t idx = (size_t)blockIdx.x*blockDim.x + threadIdx.x;   // over TT*DI/4
    int e  = (int)(idx % DI);
    int tg = (int)(idx / DI);
    int t0 = tg*4;
    int l0 = t0 & (LSEQ-1);
    const float* cw = dir ? bW : fW;
    const float* cb = dir ? bb : fb;
    const float* xz = g_xz[dir];
    float w0=cw[e*4+0], w1=cw[e*4+1], w2=cw[e*4+2], w3=cw[e*4+3];
    float bias = cb[e];
    float v[7];
    #pragma unroll
    for (int k = 0; k < 7; k++) {
        int off = k - 3;                 // input t offset -3..+3
        v[k] = (l0 + off >= 0) ? xz[(size_t)(t0+off)*(2*DI) + e] : 0.f;
    }
    float* xm = g_xm[dir];
    #pragma unroll
    for (int j = 0; j < 4; j++) {
        float acc = bias + v[j]*w0 + v[j+1]*w1 + v[j+2]*w2 + v[j+3]*w3;
        xm[(size_t)(t0+j)*DI + e] = acc / (1.f + __expf(-acc));
    }
}

// ---------------- delta: softplus(dt-row . dtW[e] + dtb), smem-staged, 4-way ILP dot ----------------
__global__ __launch_bounds__(256) void delta_k(
    const float* __restrict__ fdtW, const float* __restrict__ bdtW,
    const float* __restrict__ fdtB, const float* __restrict__ bdtB)
{
    __shared__ float sdt[TCH][DTR];      // 64 x 32 = 8 KB
    int dir = blockIdx.z;
    int e   = blockIdx.x*256 + threadIdx.x;
    int t0  = blockIdx.y*TCH;
    const float* dtW = dir ? bdtW : fdtW;
    const float  dtb = (dir ? bdtB : fdtB)[e];
    const float* dbc = g_dbc[dir];
    float* delta = g_delta[dir];

    float wr[32];
    {
        const float4* W4 = (const float4*)(dtW + (size_t)e*DTR);
        #pragma unroll
        for (int j=0;j<8;j++){ float4 v=W4[j]; wr[j*4]=v.x;wr[j*4+1]=v.y;wr[j*4+2]=v.z;wr[j*4+3]=v.w; }
    }
    // stage TCH dt rows (coalesced: dbc row stride 64, dt is first 32)
    for (int i = threadIdx.x; i < TCH*DTR; i += 256) {
        int tt = i >> 5, k = i & 31;
        sdt[tt][k] = dbc[(size_t)(t0+tt)*64 + k];
    }
    __syncthreads();
    #pragma unroll 2
    for (int j = 0; j < TCH; j++) {
        const float4* R = (const float4*)sdt[j];
        float d0=0.f, d1=0.f, d2=0.f, d3=0.f;   // 4 independent chains
        #pragma unroll
        for (int q=0;q<8;q++){
            float4 v = R[q];
            d0 += v.x*wr[q*4+0];
            d1 += v.y*wr[q*4+1];
            d2 += v.z*wr[q*4+2];
            d3 += v.w*wr[q*4+3];
        }
        float dot = dtb + ((d0+d1)+(d2+d3));
        delta[(size_t)(t0+j)*DI + e] = (dot > 20.f) ? dot : __logf(1.f + __expf(dot));
    }
}

// ---------------- scan helpers ----------------
__device__ __forceinline__ void load_negA(const float* Alog, int e, float* negA, bool& fast){
    const float4* Ar = (const float4*)(Alog + (size_t)e*16);
    #pragma unroll
    for (int s4=0;s4<4;s4++){
        float4 v=Ar[s4];
        negA[s4*4+0]=-__expf(v.x); negA[s4*4+1]=-__expf(v.y);
        negA[s4*4+2]=-__expf(v.z); negA[s4*4+3]=-__expf(v.w);
    }
    fast = true;
    #pragma unroll
    for (int s=0;s<16;s++) fast = fast && (fabsf(negA[s]+(float)(s+1)) <= 1e-3f*(float)(s+1));
}
__device__ __forceinline__ void comp_dA(float d, const float* negA, bool fast, float* da){
    if (fast){ float r=__expf(-d); da[0]=r;
        #pragma unroll
        for (int s=1;s<16;s++) da[s]=da[s-1]*r;
    } else {
        #pragma unroll
        for (int s=0;s<16;s++) da[s]=__expf(d*negA[s]);
    }
}

// ---------------- scan phase A ----------------
__global__ __launch_bounds__(256) void scanA_k(const float* __restrict__ fA, const float* __restrict__ bA)
{
    int e = blockIdx.x*256+threadIdx.x, c = blockIdx.y;
    int dir = blockIdx.z>>1, b = blockIdx.z&1;
    const float* Alog = dir?bA:fA;
    const float* delta = g_delta[dir]; const float* xm = g_xm[dir]; const float* dbc = g_dbc[dir];
    float negA[16]; bool fast; load_negA(Alog,e,negA,fast);
    float P[16], q[16];
    #pragma unroll
    for (int s=0;s<16;s++){ P[s]=1.f; q[s]=0.f; }
    int l0=c*LC;
    for (int l=l0;l<l0+LC;l++){
        int t=(b<<10)+l; size_t te=(size_t)t*DI+e;
        float d=delta[te], xv=xm[te], dx=d*xv;
        const float4* Bv=(const float4*)(dbc+(size_t)t*64+32);
        float Bsx[16];
        #pragma unroll
        for (int s4=0;s4<4;s4++){ float4 v=Bv[s4]; Bsx[s4*4]=v.x;Bsx[s4*4+1]=v.y;Bsx[s4*4+2]=v.z;Bsx[s4*4+3]=v.w; }
        float da[16]; comp_dA(d,negA,fast,da);
        #pragma unroll
        for (int s=0;s<16;s++){ q[s]=da[s]*q[s]+dx*Bsx[s]; P[s]*=da[s]; }
    }
    size_t base=(((size_t)(dir*2+b)*NC+c)*16)*DI+e;
    #pragma unroll
    for (int s=0;s<16;s++){ g_P[base+(size_t)s*DI]=P[s]; g_q[base+(size_t)s*DI]=q[s]; }
}

// ---------------- scan phase B ----------------
__global__ void scanB_k(){
    int idx = blockIdx.x*256+threadIdx.x;
    int e=idx&(DI-1), s=(idx>>10)&15, cb=idx>>14;
    float h=0.f;
    #pragma unroll 4
    for (int c=0;c<NC;c++){
        size_t base=(((size_t)cb*NC+c)*16+s)*DI+e;
        g_h0[base]=h; h=g_P[base]*h+g_q[base];
    }
}

// ---------------- scan phase C ----------------
__global__ __launch_bounds__(256) void scanC_k(const float* __restrict__ fA, const float* __restrict__ bA,
                                               const float* __restrict__ fD, const float* __restrict__ bD)
{
    int e = blockIdx.x*256+threadIdx.x, c = blockIdx.y;
    int dir = blockIdx.z>>1, b = blockIdx.z&1;
    const float* Alog = dir?bA:fA; const float* Dp = dir?bD:fD;
    const float* delta = g_delta[dir]; const float* xm = g_xm[dir];
    const float* dbc = g_dbc[dir]; const float* xz = g_xz[dir];
    float* yout = g_y[dir];
    float negA[16]; bool fast; load_negA(Alog,e,negA,fast);
    float h[16];
    size_t hb=(((size_t)(dir*2+b)*NC+c)*16)*DI+e;
    #pragma unroll
    for (int s=0;s<16;s++) h[s]=g_h0[hb+(size_t)s*DI];
    float Dpe=Dp[e];
    int l0=c*LC;
    for (int l=l0;l<l0+LC;l++){
        int t=(b<<10)+l; size_t te=(size_t)t*DI+e;
        float d=delta[te], xv=xm[te], dx=d*xv;
        const float4* BCv=(const float4*)(dbc+(size_t)t*64+32);
        float Bsx[16], Cs[16];
        #pragma unroll
        for (int s4=0;s4<4;s4++){
            float4 v=BCv[s4];   Bsx[s4*4]=v.x;Bsx[s4*4+1]=v.y;Bsx[s4*4+2]=v.z;Bsx[s4*4+3]=v.w;
            float4 w=BCv[4+s4]; Cs[s4*4]=w.x;Cs[s4*4+1]=w.y;Cs[s4*4+2]=w.z;Cs[s4*4+3]=w.w;
        }
        float da[16]; comp_dA(d,negA,fast,da);
        float y=0.f;
        #pragma unroll
        for (int s=0;s<16;s++){ h[s]=da[s]*h[s]+dx*Bsx[s]; y+=h[s]*Cs[s]; }
        float zv=xz[(size_t)t*(2*DI)+DI+e];
        float sil=zv/(1.f+__expf(-zv));
        yout[te]=(y+xv*Dpe)*sil;
    }
}

// ---------------- LN1 + LN2 + sum ----------------
__global__ void ln12_k(const float* __restrict__ x,
                       const float* __restrict__ g1, const float* __restrict__ b1,
                       const float* __restrict__ g2, const float* __restrict__ b2)
{
    __shared__ float red[4][4];
    int t=blockIdx.x, tid=threadIdx.x;
    float4 xv=((const float4*)(x+(size_t)t*DM))[tid];
    float4 fv=((const float4*)(g_dirout[0]+(size_t)t*DM))[tid];
    float4 wv=((const float4*)(g_dirout[1]+(size_t)t*DM))[tid];
    float a[4]={xv.x+fv.x,xv.y+fv.y,xv.z+fv.z,xv.w+fv.w};
    float bv[4]={xv.x+wv.x,xv.y+wv.y,xv.z+wv.z,xv.w+wv.w};
    float sa=0,sa2=0,sb=0,sb2=0;
    #pragma unroll
    for (int c=0;c<4;c++){ sa+=a[c];sa2+=a[c]*a[c];sb+=bv[c];sb2+=bv[c]*bv[c]; }
    #pragma unroll
    for (int o=16;o;o>>=1){
        sa+=__shfl_xor_sync(~0u,sa,o); sa2+=__shfl_xor_sync(~0u,sa2,o);
        sb+=__shfl_xor_sync(~0u,sb,o); sb2+=__shfl_xor_sync(~0u,sb2,o);
    }
    int w=tid>>5;
    if ((tid&31)==0){ red[0][w]=sa;red[1][w]=sa2;red[2][w]=sb;red[3][w]=sb2; }
    __syncthreads();
    float Sa=red[0][0]+red[0][1]+red[0][2]+red[0][3];
    float Sa2=red[1][0]+red[1][1]+red[1][2]+red[1][3];
    float Sb=red[2][0]+red[2][1]+red[2][2]+red[2][3];
    float Sb2=red[3][0]+red[3][1]+red[3][2]+red[3][3];
    float mua=Sa*(1.f/DM), mub=Sb*(1.f/DM);
    float ra=rsqrtf(Sa2*(1.f/DM)-mua*mua+1e-5f);
    float rb=rsqrtf(Sb2*(1.f/DM)-mub*mub+1e-5f);
    float4 o4; float* op=(float*)&o4;
    #pragma unroll
    for (int c=0;c<4;c++){
        int j=(tid<<2)+c;
        op[c]=(a[c]-mua)*ra*g1[j]+b1[j]+(bv[c]-mub)*rb*g2[j]+b2[j];
    }
    ((float4*)(g_res+(size_t)t*DM))[tid]=o4;
}

// ---------------- LN3 on 2*(ff0+ff1+b2) -> output ----------------
__global__ void ln3_k(const float* __restrict__ fb2, const float* __restrict__ g3,
                      const float* __restrict__ b3, float* __restrict__ out)
{
    __shared__ float red[2][4];
    int t=blockIdx.x, tid=threadIdx.x;
    float4 f0=((const float4*)(g_ff[0]+(size_t)t*DM))[tid];
    float4 f1=((const float4*)(g_ff[1]+(size_t)t*DM))[tid];
    float4 bb=((const float4*)fb2)[tid];
    float v[4]={2.f*(f0.x+f1.x+bb.x),2.f*(f0.y+f1.y+bb.y),2.f*(f0.z+f1.z+bb.z),2.f*(f0.w+f1.w+bb.w)};
    float s=0,s2=0;
    #pragma unroll
    for (int c=0;c<4;c++){ s+=v[c]; s2+=v[c]*v[c]; }
    #pragma unroll
    for (int o=16;o;o>>=1){ s+=__shfl_xor_sync(~0u,s,o); s2+=__shfl_xor_sync(~0u,s2,o); }
    int w=tid>>5;
    if ((tid&31)==0){ red[0][w]=s; red[1][w]=s2; }
    __syncthreads();
    float S=red[0][0]+red[0][1]+red[0][2]+red[0][3];
    float S2=red[1][0]+red[1][1]+red[1][2]+red[1][3];
    float mu=S*(1.f/DM), r=rsqrtf(S2*(1.f/DM)-mu*mu+1e-5f);
    float4 o4; float* op=(float*)&o4;
    #pragma unroll
    for (int c=0;c<4;c++){ int j=(tid<<2)+c; op[c]=(v[c]-mu)*r*g3[j]+b3[j]; }
    ((float4*)(out+(size_t)t*DM))[tid]=o4;
}

// ---------------- launch ----------------
extern "C" void kernel_launch(void* const* d_in, const int* in_sizes, int n_in,
                              void* d_out, int out_size)
{
    const float* x = (const float*)d_in[0];
    const float* inW[2]    = {(const float*)d_in[1],  (const float*)d_in[10]};
    const float* convW[2]  = {(const float*)d_in[2],  (const float*)d_in[11]};
    const float* convB[2]  = {(const float*)d_in[3],  (const float*)d_in[12]};
    const float* xprojW[2] = {(const float*)d_in[4],  (const float*)d_in[13]};
    const float* dtW[2]    = {(const float*)d_in[5],  (const float*)d_in[14]};
    const float* dtB[2]    = {(const float*)d_in[6],  (const float*)d_in[15]};
    const float* Alog[2]   = {(const float*)d_in[7],  (const float*)d_in[16]};
    const float* Dp[2]     = {(const float*)d_in[8],  (const float*)d_in[17]};
    const float* outW[2]   = {(const float*)d_in[9],  (const float*)d_in[18]};
    const float* ln1g=(const float*)d_in[19]; const float* ln1b=(const float*)d_in[20];
    const float* ln2g=(const float*)d_in[21]; const float* ln2b=(const float*)d_in[22];
    const float* ln3g=(const float*)d_in[23]; const float* ln3b=(const float*)d_in[24];
    const float* ffW1=(const float*)d_in[25]; const float* ffb1=(const float*)d_in[26];
    const float* ffW2=(const float*)d_in[27]; const float* ffb2=(const float*)d_in[28];

    float *p_xz, *p_xm, *p_dbc, *p_y, *p_dirout, *p_res, *p_h, *p_ff;
    cudaGetSymbolAddress((void**)&p_xz, g_xz);
    cudaGetSymbolAddress((void**)&p_xm, g_xm);
    cudaGetSymbolAddress((void**)&p_dbc, g_dbc);
    cudaGetSymbolAddress((void**)&p_y, g_y);
    cudaGetSymbolAddress((void**)&p_dirout, g_dirout);
    cudaGetSymbolAddress((void**)&p_res, g_res);
    cudaGetSymbolAddress((void**)&p_h, g_hbuf);
    cudaGetSymbolAddress((void**)&p_ff, g_ff);

    const size_t xzStride=(size_t)TT*2*DI, diStride=(size_t)TT*DI,
                 dbcStride=(size_t)TT*64, dmStride=(size_t)TT*DM;

    const int SMEM = 65536;
    cudaFuncSetAttribute(gemm_tf32, cudaFuncAttributeMaxDynamicSharedMemorySize, SMEM);

    // zero split-K accumulation target (xproj only)
    cudaMemsetAsync(p_dbc, 0, (size_t)2*TT*64*sizeof(float));

    // 1) input projection (both dirs fused; dir1 reads flipped rows)
    {
        GemmArgs a0 = {x, inW[0], nullptr, p_xz,            0, 0};
        GemmArgs a1 = {x, inW[1], nullptr, p_xz + xzStride, 1, 0};
        gemm_tf32<<<dim3((2*DI)/128, TT/128, 2), 512, SMEM>>>(a0, a1, TT, 2*DI, DM, DM, DM, 2*DI, 0, 1);
    }

    // 2) depthwise causal conv + silu (4 timesteps per thread)
    conv_silu_k<<<dim3((unsigned)((size_t)TT*DI/4/256), 2), 256>>>(
        convW[0], convB[0], convW[1], convB[1]);

    // 3a) dbc = xm @ xproj^T   (split-K=8, both dirs -> z=16, atomics)
    {
        GemmArgs a0 = {p_xm,          xprojW[0], nullptr, p_dbc};
        GemmArgs a1 = {p_xm+diStride, xprojW[1], nullptr, p_dbc+dbcStride};
        gemm_tf32<<<dim3(1, TT/128, 16), 512, SMEM>>>(a0, a1, TT, 64, DI, DI, DI, 64, 0, 8);
    }
    // 3b) delta = softplus(dt @ dtW^T + dtb)  — SIMT, smem-staged, ILP dot
    delta_k<<<dim3(DI/256, TT/TCH, 2), 256>>>(dtW[0], dtW[1], dtB[0], dtB[1]);

    // 4) chunked selective scan
    scanA_k<<<dim3(DI/256, NC, 2*NBATCH), 256>>>(Alog[0], Alog[1]);
    scanB_k<<<(2*NBATCH*DI*DS)/256, 256>>>();
    scanC_k<<<dim3(DI/256, NC, 2*NBATCH), 256>>>(Alog[0], Alog[1], Dp[0], Dp[1]);

    // 5) output projection (dir1 writes flipped rows)
    {
        GemmArgs a0 = {p_y,          outW[0], nullptr, p_dirout,          0, 0};
        GemmArgs a1 = {p_y+diStride, outW[1], nullptr, p_dirout+dmStride, 0, 1};
        gemm_tf32<<<dim3(DM/128, TT/128, 2), 512, SMEM>>>(a0, a1, TT, DM, DI, DI, DI, DM, 0, 1);
    }

    // 6) an1 + an2
    ln12_k<<<TT, 128>>>(x, ln1g, ln1b, ln2g, ln2b);

    // 7) FFN
    {
        GemmArgs a0 = {p_res, ffW1, ffb1, p_h, 0, 0};
        gemm_tf32<<<dim3(DFF/128, TT/128, 1), 512, SMEM>>>(a0, a0, TT, DFF, DM, DM, DM, DFF, 1, 1);
    }
    {
        // split-K=2 via pointer-offset halves into two disjoint buffers (no atomics)
        GemmArgs a0 = {p_h,         ffW2,         nullptr, p_ff,          0, 0};
        GemmArgs a1 = {p_h + DFF/2, ffW2 + DFF/2, nullptr, p_ff+dmStride, 0, 0};
        gemm_tf32<<<dim3(DM/128, TT/128, 2), 512, SMEM>>>(a0, a1, TT, DM, DFF/2, DFF, DFF, DM, 0, 1);
    }

    // 8) LN(2*(ff0+ff1+b2)) -> output
    ln3_k<<<TT, 128>>>(ffb2, ln3g, ln3b, (float*)d_out);
}

// round 17
// speedup vs baseline: 1.5610x; 1.0135x over previous
#include <cuda_runtime.h>
#include <math.h>

// ---------------- problem constants ----------------
#define LSEQ   1024
#define NBATCH 2
#define TT     (NBATCH*LSEQ)   // 2048 tokens
#define DM     512
#define DI     1024
#define DFF    2048
#define DS     16
#define DTR    32
#define NC     32              // scan chunks
#define LC     (LSEQ/NC)       // 32 steps per chunk

// ---------------- scratch ----------------
__device__ float g_xz[2][(size_t)TT*2*DI];
__device__ float g_xm[2][(size_t)TT*DI];
__device__ float g_dbc[2][(size_t)TT*64];
__device__ float g_delta[2][(size_t)TT*DI];
__device__ float g_y[2][(size_t)TT*DI];
__device__ float g_dirout[2][(size_t)TT*DM];
__device__ float g_res[(size_t)TT*DM];
__device__ float g_hbuf[(size_t)TT*DFF];
__device__ float g_ff[2][(size_t)TT*DM];      // two split-K partial buffers
__device__ float g_P [(size_t)2*NBATCH*NC*DS*DI];
__device__ float g_q [(size_t)2*NBATCH*NC*DS*DI];
__device__ float g_h0[(size_t)2*NBATCH*NC*DS*DI];

// ---------------- TF32 tensor-core GEMM ----------------
// C[M,N] = A[M,K] * W[N,K]^T ; A row-major (lda), W row-major (ldb).
// CTA tile 128x128xKT32, 512 threads, 16 warps of 32x32 warp tiles.
// SMEM in MMA-fragment-interleaved layout, XOR bank swizzle; frag loads are
// 1x LDS.128 (A) / 1x LDS.64 (B), conflict-free.
struct GemmArgs { const float* A; const float* W; const float* bias; float* C; int flipA; int flipC; };

#define KT 32

__device__ __forceinline__ unsigned f2tf32(float f) {
    unsigned u; asm("cvt.rna.tf32.f32 %0, %1;" : "=r"(u) : "f"(f)); return u;
}
__device__ __forceinline__ float cvtf(float f) { return __uint_as_float(f2tf32(f)); }

__global__ __launch_bounds__(512,1) void gemm_tf32(
    GemmArgs ga0, GemmArgs ga1, int M, int N, int K, int lda, int ldb, int ldc, int mode, int S)
{
    extern __shared__ float sh[];
    float* shA = sh; float* shB = sh + 8192;
    const int z = blockIdx.z;
    const int dir = z / S, sk = z - dir*S;
    const GemmArgs g = dir ? ga1 : ga0;
    const int kLen = K/S, kOff = sk*kLen;
    const int tid = threadIdx.x, lane = tid&31, w = tid>>5;
    const int gq = lane>>2, tq = lane&3;
    const int wm = (w&3)*32, wn = (w>>2)*32;
    const int wgm = (w&3)*2, wgn = (w>>2)*4;
    const int m0 = blockIdx.y*128, n0 = blockIdx.x*128;
    const int lr = tid>>3, lc4 = (tid&7)*4;
    const int ksl = lc4>>3, khalf = (lc4>>2)&1;

    size_t aRow[2], bRow[2];
    #pragma unroll
    for (int i=0;i<2;i++){
        int m = m0+lr+i*64;
        int r = m;
        if (g.flipA) r = (m&~(LSEQ-1)) + (LSEQ-1 - (m&(LSEQ-1)));
        aRow[i] = (size_t)r*lda + kOff;
    }
    #pragma unroll
    for (int i=0;i<2;i++){ int n=n0+lr+i*64; if(n>=N)n=N-1; bRow[i]=(size_t)n*ldb+kOff; }
    int aBase[2], bBase[2];
    #pragma unroll
    for (int i=0;i<2;i++){
        int m=lr+i*64; int gg=m>>4, gq_=m&7, mh=(m>>3)&1;
        aBase[i]=((((gg*4+ksl)*8+gq_)<<4))+khalf*2+mh;
        int gb=m>>3, gqb=m&7;
        bBase[i]=((((gb*4+ksl)*8+gqb)<<3))+khalf;
    }
    float4 aReg[2], bReg[2];
    #pragma unroll
    for (int i=0;i<2;i++) aReg[i]=*(const float4*)(g.A+aRow[i]+lc4);
    #pragma unroll
    for (int i=0;i<2;i++) bReg[i]=*(const float4*)(g.W+bRow[i]+lc4);
    float c[2][4][4];
    #pragma unroll
    for (int mt=0;mt<2;mt++) for (int nt=0;nt<4;nt++) for (int r=0;r<4;r++) c[mt][nt][r]=0.f;
    int buf=0;
    #pragma unroll
    for (int i=0;i<2;i++){
        float* p=shA+aBase[i]; float v[4]={aReg[i].x,aReg[i].y,aReg[i].z,aReg[i].w};
        #pragma unroll
        for(int j=0;j<4;j++) p[(j^ksl)<<2]=cvtf(v[j]);
        float* q=shB+bBase[i]; float u[4]={bReg[i].x,bReg[i].y,bReg[i].z,bReg[i].w};
        #pragma unroll
        for(int j=0;j<4;j++) q[(j^ksl)<<1]=cvtf(u[j]);
    }
    __syncthreads();
    for (int kt=0; kt<kLen; kt+=KT){
        bool more = (kt+KT)<kLen;
        if (more){
            #pragma unroll
            for (int i=0;i<2;i++) aReg[i]=*(const float4*)(g.A+aRow[i]+kt+KT+lc4);
            #pragma unroll
            for (int i=0;i<2;i++) bReg[i]=*(const float4*)(g.W+bRow[i]+kt+KT+lc4);
        }
        const float4* Ap=(const float4*)(shA+buf*4096);
        const float2* Bp=(const float2*)(shB+buf*4096);
        #pragma unroll
        for (int ks=0;ks<4;ks++){
            const int tqp=tq^ks;
            float4 av[2]; float2 bv[4];
            #pragma unroll
            for (int mt=0;mt<2;mt++) av[mt]=Ap[(((wgm+mt)*4+ks)*8+gq)*4+tqp];
            #pragma unroll
            for (int nt=0;nt<4;nt++) bv[nt]=Bp[(((wgn+nt)*4+ks)*8+gq)*4+tqp];
            #pragma unroll
            for (int mt=0;mt<2;mt++)
                #pragma unroll
                for (int nt=0;nt<4;nt++)
                    asm volatile("mma.sync.aligned.m16n8k8.row.col.f32.tf32.tf32.f32 {%0,%1,%2,%3}, {%4,%5,%6,%7}, {%8,%9}, {%0,%1,%2,%3};"
                        : "+f"(c[mt][nt][0]),"+f"(c[mt][nt][1]),"+f"(c[mt][nt][2]),"+f"(c[mt][nt][3])
                        : "r"(__float_as_uint(av[mt].x)),"r"(__float_as_uint(av[mt].y)),
                          "r"(__float_as_uint(av[mt].z)),"r"(__float_as_uint(av[mt].w)),
                          "r"(__float_as_uint(bv[nt].x)),"r"(__float_as_uint(bv[nt].y)));
        }
        if (more){
            int nb=buf^1;
            #pragma unroll
            for (int i=0;i<2;i++){
                float* p=shA+nb*4096+aBase[i]; float v[4]={aReg[i].x,aReg[i].y,aReg[i].z,aReg[i].w};
                #pragma unroll
                for(int j=0;j<4;j++) p[(j^ksl)<<2]=cvtf(v[j]);
                float* q=shB+nb*4096+bBase[i]; float u[4]={bReg[i].x,bReg[i].y,bReg[i].z,bReg[i].w};
                #pragma unroll
                for(int j=0;j<4;j++) q[(j^ksl)<<1]=cvtf(u[j]);
            }
        }
        __syncthreads();
        buf^=1;
    }
    #pragma unroll
    for (int mt=0;mt<2;mt++)
        #pragma unroll
        for (int half=0;half<2;half++){
            int m = m0 + wm + mt*16 + gq + half*8;
            int orow = m;
            if (g.flipC) orow = (m&~(LSEQ-1)) + (LSEQ-1 - (m&(LSEQ-1)));
            #pragma unroll
            for (int nt=0;nt<4;nt++){
                int col = n0 + wn + nt*8 + 2*tq;
                if (col>=N) continue;
                float v0=c[mt][nt][half*2+0], v1=c[mt][nt][half*2+1];
                if (S>1){
                    atomicAdd(g.C+(size_t)orow*ldc+col, v0);
                    atomicAdd(g.C+(size_t)orow*ldc+col+1, v1);
                } else {
                    if (mode){ v0+=g.bias[col]; v1+=g.bias[col+1]; }
                    if (mode==1){ v0=fmaxf(v0,0.f); v1=fmaxf(v1,0.f); }
                    else if (mode==2){
                        v0=(v0>20.f)?v0:__logf(1.f+__expf(v0));
                        v1=(v1>20.f)?v1:__logf(1.f+__expf(v1));
                    }
                    *(float2*)(g.C+(size_t)orow*ldc+col)=make_float2(v0,v1);
                }
            }
        }
}

// ---------------- causal depthwise conv (width 4) + silu, 4 t per thread ----------------
__global__ void conv_silu_k(const float* __restrict__ fW, const float* __restrict__ fb,
                            const float* __restrict__ bW, const float* __restrict__ bb)
{
    int dir = blockIdx.y;
    size_t idx = (size_t)blockIdx.x*blockDim.x + threadIdx.x;   // over TT*DI/4
    int e  = (int)(idx % DI);
    int tg = (int)(idx / DI);
    int t0 = tg*4;
    int l0 = t0 & (LSEQ-1);
    const float* cw = dir ? bW : fW;
    const float* cb = dir ? bb : fb;
    const float* xz = g_xz[dir];
    float w0=cw[e*4+0], w1=cw[e*4+1], w2=cw[e*4+2], w3=cw[e*4+3];
    float bias = cb[e];
    float v[7];
    #pragma unroll
    for (int k = 0; k < 7; k++) {
        int off = k - 3;                 // input t offset -3..+3
        v[k] = (l0 + off >= 0) ? xz[(size_t)(t0+off)*(2*DI) + e] : 0.f;
    }
    float* xm = g_xm[dir];
    #pragma unroll
    for (int j = 0; j < 4; j++) {
        // output t0+j uses inputs (t0+j-3 .. t0+j) = v[j..j+3]
        float acc = bias + v[j]*w0 + v[j+1]*w1 + v[j+2]*w2 + v[j+3]*w3;
        xm[(size_t)(t0+j)*DI + e] = acc / (1.f + __expf(-acc));
    }
}

// ---------------- scan helpers ----------------
__device__ __forceinline__ void load_negA(const float* Alog, int e, float* negA, bool& fast){
    const float4* Ar = (const float4*)(Alog + (size_t)e*16);
    #pragma unroll
    for (int s4=0;s4<4;s4++){
        float4 v=Ar[s4];
        negA[s4*4+0]=-__expf(v.x); negA[s4*4+1]=-__expf(v.y);
        negA[s4*4+2]=-__expf(v.z); negA[s4*4+3]=-__expf(v.w);
    }
    fast = true;
    #pragma unroll
    for (int s=0;s<16;s++) fast = fast && (fabsf(negA[s]+(float)(s+1)) <= 1e-3f*(float)(s+1));
}
__device__ __forceinline__ void comp_dA(float d, const float* negA, bool fast, float* da){
    if (fast){ float r=__expf(-d); da[0]=r;
        #pragma unroll
        for (int s=1;s<16;s++) da[s]=da[s-1]*r;
    } else {
        #pragma unroll
        for (int s=0;s<16;s++) da[s]=__expf(d*negA[s]);
    }
}

// ---------------- scan phase A ----------------
__global__ __launch_bounds__(256) void scanA_k(const float* __restrict__ fA, const float* __restrict__ bA)
{
    int e = blockIdx.x*256+threadIdx.x, c = blockIdx.y;
    int dir = blockIdx.z>>1, b = blockIdx.z&1;
    const float* Alog = dir?bA:fA;
    const float* delta = g_delta[dir]; const float* xm = g_xm[dir]; const float* dbc = g_dbc[dir];
    float negA[16]; bool fast; load_negA(Alog,e,negA,fast);
    float P[16], q[16];
    #pragma unroll
    for (int s=0;s<16;s++){ P[s]=1.f; q[s]=0.f; }
    int l0=c*LC;
    for (int l=l0;l<l0+LC;l++){
        int t=(b<<10)+l; size_t te=(size_t)t*DI+e;
        float d=delta[te], xv=xm[te], dx=d*xv;
        const float4* Bv=(const float4*)(dbc+(size_t)t*64+32);
        float Bsx[16];
        #pragma unroll
        for (int s4=0;s4<4;s4++){ float4 v=Bv[s4]; Bsx[s4*4]=v.x;Bsx[s4*4+1]=v.y;Bsx[s4*4+2]=v.z;Bsx[s4*4+3]=v.w; }
        float da[16]; comp_dA(d,negA,fast,da);
        #pragma unroll
        for (int s=0;s<16;s++){ q[s]=da[s]*q[s]+dx*Bsx[s]; P[s]*=da[s]; }
    }
    size_t base=(((size_t)(dir*2+b)*NC+c)*16)*DI+e;
    #pragma unroll
    for (int s=0;s<16;s++){ g_P[base+(size_t)s*DI]=P[s]; g_q[base+(size_t)s*DI]=q[s]; }
}

// ---------------- scan phase B ----------------
__global__ void scanB_k(){
    int idx = blockIdx.x*256+threadIdx.x;
    int e=idx&(DI-1), s=(idx>>10)&15, cb=idx>>14;
    float h=0.f;
    #pragma unroll 4
    for (int c=0;c<NC;c++){
        size_t base=(((size_t)cb*NC+c)*16+s)*DI+e;
        g_h0[base]=h; h=g_P[base]*h+g_q[base];
    }
}

// ---------------- scan phase C ----------------
__global__ __launch_bounds__(256) void scanC_k(const float* __restrict__ fA, const float* __restrict__ bA,
                                               const float* __restrict__ fD, const float* __restrict__ bD)
{
    int e = blockIdx.x*256+threadIdx.x, c = blockIdx.y;
    int dir = blockIdx.z>>1, b = blockIdx.z&1;
    const float* Alog = dir?bA:fA; const float* Dp = dir?bD:fD;
    const float* delta = g_delta[dir]; const float* xm = g_xm[dir];
    const float* dbc = g_dbc[dir]; const float* xz = g_xz[dir];
    float* yout = g_y[dir];
    float negA[16]; bool fast; load_negA(Alog,e,negA,fast);
    float h[16];
    size_t hb=(((size_t)(dir*2+b)*NC+c)*16)*DI+e;
    #pragma unroll
    for (int s=0;s<16;s++) h[s]=g_h0[hb+(size_t)s*DI];
    float Dpe=Dp[e];
    int l0=c*LC;
    for (int l=l0;l<l0+LC;l++){
        int t=(b<<10)+l; size_t te=(size_t)t*DI+e;
        float d=delta[te], xv=xm[te], dx=d*xv;
        const float4* BCv=(const float4*)(dbc+(size_t)t*64+32);
        float Bsx[16], Cs[16];
        #pragma unroll
        for (int s4=0;s4<4;s4++){
            float4 v=BCv[s4];   Bsx[s4*4]=v.x;Bsx[s4*4+1]=v.y;Bsx[s4*4+2]=v.z;Bsx[s4*4+3]=v.w;
            float4 w=BCv[4+s4]; Cs[s4*4]=w.x;Cs[s4*4+1]=w.y;Cs[s4*4+2]=w.z;Cs[s4*4+3]=w.w;
        }
        float da[16]; comp_dA(d,negA,fast,da);
        float y=0.f;
        #pragma unroll
        for (int s=0;s<16;s++){ h[s]=da[s]*h[s]+dx*Bsx[s]; y+=h[s]*Cs[s]; }
        float zv=xz[(size_t)t*(2*DI)+DI+e];
        float sil=zv/(1.f+__expf(-zv));
        yout[te]=(y+xv*Dpe)*sil;
    }
}

// ---------------- LN1 + LN2 + sum ----------------
__global__ void ln12_k(const float* __restrict__ x,
                       const float* __restrict__ g1, const float* __restrict__ b1,
                       const float* __restrict__ g2, const float* __restrict__ b2)
{
    __shared__ float red[4][4];
    int t=blockIdx.x, tid=threadIdx.x;
    float4 xv=((const float4*)(x+(size_t)t*DM))[tid];
    float4 fv=((const float4*)(g_dirout[0]+(size_t)t*DM))[tid];
    float4 wv=((const float4*)(g_dirout[1]+(size_t)t*DM))[tid];
    float a[4]={xv.x+fv.x,xv.y+fv.y,xv.z+fv.z,xv.w+fv.w};
    float bv[4]={xv.x+wv.x,xv.y+wv.y,xv.z+wv.z,xv.w+wv.w};
    float sa=0,sa2=0,sb=0,sb2=0;
    #pragma unroll
    for (int c=0;c<4;c++){ sa+=a[c];sa2+=a[c]*a[c];sb+=bv[c];sb2+=bv[c]*bv[c]; }
    #pragma unroll
    for (int o=16;o;o>>=1){
        sa+=__shfl_xor_sync(~0u,sa,o); sa2+=__shfl_xor_sync(~0u,sa2,o);
        sb+=__shfl_xor_sync(~0u,sb,o); sb2+=__shfl_xor_sync(~0u,sb2,o);
    }
    int w=tid>>5;
    if ((tid&31)==0){ red[0][w]=sa;red[1][w]=sa2;red[2][w]=sb;red[3][w]=sb2; }
    __syncthreads();
    float Sa=red[0][0]+red[0][1]+red[0][2]+red[0][3];
    float Sa2=red[1][0]+red[1][1]+red[1][2]+red[1][3];
    float Sb=red[2][0]+red[2][1]+red[2][2]+red[2][3];
    float Sb2=red[3][0]+red[3][1]+red[3][2]+red[3][3];
    float mua=Sa*(1.f/DM), mub=Sb*(1.f/DM);
    float ra=rsqrtf(Sa2*(1.f/DM)-mua*mua+1e-5f);
    float rb=rsqrtf(Sb2*(1.f/DM)-mub*mub+1e-5f);
    float4 o4; float* op=(float*)&o4;
    #pragma unroll
    for (int c=0;c<4;c++){
        int j=(tid<<2)+c;
        op[c]=(a[c]-mua)*ra*g1[j]+b1[j]+(bv[c]-mub)*rb*g2[j]+b2[j];
    }
    ((float4*)(g_res+(size_t)t*DM))[tid]=o4;
}

// ---------------- LN3 on 2*(ff0+ff1+b2) -> output ----------------
__global__ void ln3_k(const float* __restrict__ fb2, const float* __restrict__ g3,
                      const float* __restrict__ b3, float* __restrict__ out)
{
    __shared__ float red[2][4];
    int t=blockIdx.x, tid=threadIdx.x;
    float4 f0=((const float4*)(g_ff[0]+(size_t)t*DM))[tid];
    float4 f1=((const float4*)(g_ff[1]+(size_t)t*DM))[tid];
    float4 bb=((const float4*)fb2)[tid];
    float v[4]={2.f*(f0.x+f1.x+bb.x),2.f*(f0.y+f1.y+bb.y),2.f*(f0.z+f1.z+bb.z),2.f*(f0.w+f1.w+bb.w)};
    float s=0,s2=0;
    #pragma unroll
    for (int c=0;c<4;c++){ s+=v[c]; s2+=v[c]*v[c]; }
    #pragma unroll
    for (int o=16;o;o>>=1){ s+=__shfl_xor_sync(~0u,s,o); s2+=__shfl_xor_sync(~0u,s2,o); }
    int w=tid>>5;
    if ((tid&31)==0){ red[0][w]=s; red[1][w]=s2; }
    __syncthreads();
    float S=red[0][0]+red[0][1]+red[0][2]+red[0][3];
    float S2=red[1][0]+red[1][1]+red[1][2]+red[1][3];
    float mu=S*(1.f/DM), r=rsqrtf(S2*(1.f/DM)-mu*mu+1e-5f);
    float4 o4; float* op=(float*)&o4;
    #pragma unroll
    for (int c=0;c<4;c++){ int j=(tid<<2)+c; op[c]=(v[c]-mu)*r*g3[j]+b3[j]; }
    ((float4*)(out+(size_t)t*DM))[tid]=o4;
}

// ---------------- launch ----------------
extern "C" void kernel_launch(void* const* d_in, const int* in_sizes, int n_in,
                              void* d_out, int out_size)
{
    const float* x = (const float*)d_in[0];
    const float* inW[2]    = {(const float*)d_in[1],  (const float*)d_in[10]};
    const float* convW[2]  = {(const float*)d_in[2],  (const float*)d_in[11]};
    const float* convB[2]  = {(const float*)d_in[3],  (const float*)d_in[12]};
    const float* xprojW[2] = {(const float*)d_in[4],  (const float*)d_in[13]};
    const float* dtW[2]    = {(const float*)d_in[5],  (const float*)d_in[14]};
    const float* dtB[2]    = {(const float*)d_in[6],  (const float*)d_in[15]};
    const float* Alog[2]   = {(const float*)d_in[7],  (const float*)d_in[16]};
    const float* Dp[2]     = {(const float*)d_in[8],  (const float*)d_in[17]};
    const float* outW[2]   = {(const float*)d_in[9],  (const float*)d_in[18]};
    const float* ln1g=(const float*)d_in[19]; const float* ln1b=(const float*)d_in[20];
    const float* ln2g=(const float*)d_in[21]; const float* ln2b=(const float*)d_in[22];
    const float* ln3g=(const float*)d_in[23]; const float* ln3b=(const float*)d_in[24];
    const float* ffW1=(const float*)d_in[25]; const float* ffb1=(const float*)d_in[26];
    const float* ffW2=(const float*)d_in[27]; const float* ffb2=(const float*)d_in[28];

    float *p_xz, *p_xm, *p_dbc, *p_delta, *p_y, *p_dirout, *p_res, *p_h, *p_ff;
    cudaGetSymbolAddress((void**)&p_xz, g_xz);
    cudaGetSymbolAddress((void**)&p_xm, g_xm);
    cudaGetSymbolAddress((void**)&p_dbc, g_dbc);
    cudaGetSymbolAddress((void**)&p_delta, g_delta);
    cudaGetSymbolAddress((void**)&p_y, g_y);
    cudaGetSymbolAddress((void**)&p_dirout, g_dirout);
    cudaGetSymbolAddress((void**)&p_res, g_res);
    cudaGetSymbolAddress((void**)&p_h, g_hbuf);
    cudaGetSymbolAddress((void**)&p_ff, g_ff);

    const size_t xzStride=(size_t)TT*2*DI, diStride=(size_t)TT*DI,
                 dbcStride=(size_t)TT*64, dmStride=(size_t)TT*DM;

    const int SMEM = 65536;
    cudaFuncSetAttribute(gemm_tf32, cudaFuncAttributeMaxDynamicSharedMemorySize, SMEM);

    // zero split-K accumulation target (xproj only)
    cudaMemsetAsync(p_dbc, 0, (size_t)2*TT*64*sizeof(float));

    // 1) input projection (both dirs fused; dir1 reads flipped rows)
    {
        GemmArgs a0 = {x, inW[0], nullptr, p_xz,            0, 0};
        GemmArgs a1 = {x, inW[1], nullptr, p_xz + xzStride, 1, 0};
        gemm_tf32<<<dim3((2*DI)/128, TT/128, 2), 512, SMEM>>>(a0, a1, TT, 2*DI, DM, DM, DM, 2*DI, 0, 1);
    }

    // 2) depthwise causal conv + silu (4 timesteps per thread)
    conv_silu_k<<<dim3((unsigned)((size_t)TT*DI/4/256), 2), 256>>>(
        convW[0], convB[0], convW[1], convB[1]);

    // 3a) dbc = xm @ xproj^T   (split-K=8, both dirs -> z=16, atomics)
    {
        GemmArgs a0 = {p_xm,          xprojW[0], nullptr, p_dbc};
        GemmArgs a1 = {p_xm+diStride, xprojW[1], nullptr, p_dbc+dbcStride};
        gemm_tf32<<<dim3(1, TT/128, 16), 512, SMEM>>>(a0, a1, TT, 64, DI, DI, DI, 64, 0, 8);
    }
    // 3b) delta = softplus(dt @ dtW^T + dtb)
    {
        GemmArgs a0 = {p_dbc,           dtW[0], dtB[0], p_delta};
        GemmArgs a1 = {p_dbc+dbcStride, dtW[1], dtB[1], p_delta+diStride};
        gemm_tf32<<<dim3(DI/128, TT/128, 2), 512, SMEM>>>(a0, a1, TT, DI, DTR, 64, DTR, DI, 2, 1);
    }

    // 4) chunked selective scan
    scanA_k<<<dim3(DI/256, NC, 2*NBATCH), 256>>>(Alog[0], Alog[1]);
    scanB_k<<<(2*NBATCH*DI*DS)/256, 256>>>();
    scanC_k<<<dim3(DI/256, NC, 2*NBATCH), 256>>>(Alog[0], Alog[1], Dp[0], Dp[1]);

    // 5) output projection (dir1 writes flipped rows)
    {
        GemmArgs a0 = {p_y,          outW[0], nullptr, p_dirout,          0, 0};
        GemmArgs a1 = {p_y+diStride, outW[1], nullptr, p_dirout+dmStride, 0, 1};
        gemm_tf32<<<dim3(DM/128, TT/128, 2), 512, SMEM>>>(a0, a1, TT, DM, DI, DI, DI, DM, 0, 1);
    }

    // 6) an1 + an2
    ln12_k<<<TT, 128>>>(x, ln1g, ln1b, ln2g, ln2b);

    // 7) FFN
    {
        GemmArgs a0 = {p_res, ffW1, ffb1, p_h, 0, 0};
        gemm_tf32<<<dim3(DFF/128, TT/128, 1), 512, SMEM>>>(a0, a0, TT, DFF, DM, DM, DM, DFF, 1, 1);
    }
    {
        // split-K=2 via pointer-offset halves into two disjoint buffers (no atomics)
        GemmArgs a0 = {p_h,         ffW2,         nullptr, p_ff,          0, 0};
        GemmArgs a1 = {p_h + DFF/2, ffW2 + DFF/2, nullptr, p_ff+dmStride, 0, 0};
        gemm_tf32<<<dim3(DM/128, TT/128, 2), 512, SMEM>>>(a0, a1, TT, DM, DFF/2, DFF, DFF, DM, 0, 1);
    }

    // 8) LN(2*(ff0+ff1+b2)) -> output
    ln3_k<<<TT, 128>>>(ffb2, ln3g, ln3b, (float*)d_out);
}